// round 4
// baseline (speedup 1.0000x reference)
#include <cuda_runtime.h>
#include <cstdint>

// ---------------- problem constants ----------------
#define BATCH   4096
#define FRAME   267
#define LATENT  32
#define HIDDEN  256
#define GATE_H  64
#define EXPERTS 6
#define IN0     (LATENT + FRAME)    // 299
#define IN1     (LATENT + HIDDEN)   // 288
#define OUTD    FRAME               // 267

#define OFF_MU  (BATCH * OUTD)
#define OFF_LV  (OFF_MU + BATCH * LATENT)

// ---------------- scratch (allocation-free) ----------------
__device__ float g_h1[BATCH * HIDDEN];
__device__ float g_h2[BATCH * HIDDEN];
__device__ float g_zbuf[BATCH * LATENT];
__device__ float g_coef[BATCH * EXPERTS];
__device__ float g_d1[BATCH * HIDDEN];
__device__ float g_d2[BATCH * HIDDEN];

__device__ __forceinline__ float elu1(float x) { return x > 0.f ? x : expm1f(x); }

__device__ __forceinline__ float tf32r(float x) {
    float y;
    asm("cvt.rna.tf32.f32 %0, %1;" : "=f"(y) : "f"(x));
    return y;
}

// ============================================================
// gemm128: 64x32 tile, 128 threads = 4 warps, warp tile m16n32
// (the proven R2 inner loop / addressing, halved BN for 2x grid).
//   C[m,n] = act( inp[m,:] @ W[:,n] + bias )          (E_ == 1)
//   C[m,n] = act( sum_e cf[m,e]*(inp@W_e)[m,n] + cf@b ) (E_ > 1)
// inp[m,i] = i<K0 ? A0[m,i] : A1[m,i-K0]
// ============================================================
template<int N_, int K0_, int DIN_, int E_, int ACT_>
__global__ __launch_bounds__(128) void gemm128(
    const float* __restrict__ A0, int lda0,
    const float* __restrict__ A1, int lda1,
    const float* __restrict__ coeff,
    const float* __restrict__ W, const float* __restrict__ bias,
    float* __restrict__ C, int ldc)
{
    __shared__ float As[64][36];   // [m][k]: consumer bank = (m*4+k)%32, conflict-free
    __shared__ float Bs[32][40];   // [k][n]: consumer bank = (k*8+n)%32, conflict-free

    const int tid  = threadIdx.x;
    const int lane = tid & 31;
    const int wid  = tid >> 5;          // 0..3
    const int wm16 = wid << 4;          // warp rows 0,16,32,48
    const int gid  = lane >> 2;
    const int tg   = lane & 3;

    const int bm_ = blockIdx.y * 64;
    const int bn_ = blockIdx.x * 32;

    // producers: A 64x32/128thr = 16 ea ; B 32x32/128thr = 8 ea
    const int am  = tid >> 1;           // 0..63
    const int ak0 = (tid & 1) << 4;     // 0,16
    const int bkL = tid >> 3;           // 0..15 (+16)
    const int bn0 = (tid & 7) << 2;     // 0..28

    const int r0 = bm_ + wm16 + gid;
    const int r1 = r0 + 8;

    float cf0[E_], cf1[E_];
    if (E_ > 1) {
        #pragma unroll
        for (int e = 0; e < E_; e++) {
            cf0[e] = __ldg(&coeff[r0 * E_ + e]);
            cf1[e] = __ldg(&coeff[r1 * E_ + e]);
        }
    }

    constexpr int NTILE = (DIN_ + 31) / 32;
    float tot[4][4] = {};

    for (int e = 0; e < E_; e++) {
        float acc[4][4] = {};
        const float* We = W + (size_t)e * DIN_ * N_;

        for (int tt = 0; tt < NTILE; tt++) {
            const int kt = tt * 32;
            // ---- A tile (concat, zero-pad tail) ----
            #pragma unroll
            for (int j = 0; j < 16; j++) {
                const int i = kt + ak0 + j;
                float v = 0.f;
                if ((DIN_ % 32 == 0) || i < DIN_)
                    v = (i < K0_) ? __ldg(&A0[(bm_ + am) * lda0 + i])
                                  : __ldg(&A1[(bm_ + am) * lda1 + (i - K0_)]);
                As[am][ak0 + j] = tf32r(v);
            }
            // ---- B tile ----
            #pragma unroll
            for (int h = 0; h < 2; h++) {
                const int kl = bkL + h * 16;
                const int kg = kt + kl;
                const bool kok = (DIN_ % 32 == 0) || (kg < DIN_);
                #pragma unroll
                for (int j = 0; j < 4; j++) {
                    const int n = bn_ + bn0 + j;
                    float v = 0.f;
                    if (kok && ((N_ % 32) == 0 || n < N_))
                        v = __ldg(&We[(size_t)kg * N_ + n]);
                    Bs[kl][bn0 + j] = tf32r(v);
                }
            }
            __syncthreads();

            #pragma unroll
            for (int ks = 0; ks < 4; ks++) {
                const int kk = ks << 3;
                uint32_t a0 = __float_as_uint(As[wm16 + gid    ][kk + tg    ]);
                uint32_t a1 = __float_as_uint(As[wm16 + gid + 8][kk + tg    ]);
                uint32_t a2 = __float_as_uint(As[wm16 + gid    ][kk + tg + 4]);
                uint32_t a3 = __float_as_uint(As[wm16 + gid + 8][kk + tg + 4]);
                #pragma unroll
                for (int t = 0; t < 4; t++) {
                    const int col = (t << 3) + gid;
                    uint32_t b0 = __float_as_uint(Bs[kk + tg    ][col]);
                    uint32_t b1 = __float_as_uint(Bs[kk + tg + 4][col]);
                    asm volatile(
                        "mma.sync.aligned.m16n8k8.row.col.f32.tf32.tf32.f32 "
                        "{%0,%1,%2,%3}, {%4,%5,%6,%7}, {%8,%9}, {%0,%1,%2,%3};\n"
                        : "+f"(acc[t][0]), "+f"(acc[t][1]),
                          "+f"(acc[t][2]), "+f"(acc[t][3])
                        : "r"(a0), "r"(a1), "r"(a2), "r"(a3), "r"(b0), "r"(b1));
                }
            }
            __syncthreads();
        }

        if (E_ > 1) {
            #pragma unroll
            for (int t = 0; t < 4; t++) {
                #pragma unroll
                for (int q = 0; q < 4; q++)
                    tot[t][q] = fmaf((q < 2) ? cf0[e] : cf1[e], acc[t][q], tot[t][q]);
            }
        } else {
            #pragma unroll
            for (int t = 0; t < 4; t++)
                #pragma unroll
                for (int q = 0; q < 4; q++) tot[t][q] = acc[t][q];
        }
    }

    // ---- epilogue ----
    #pragma unroll
    for (int t = 0; t < 4; t++) {
        #pragma unroll
        for (int q = 0; q < 4; q++) {
            const int r    = (q < 2) ? r0 : r1;
            const int colL = (t << 3) + (tg << 1) + (q & 1);
            const int cG   = bn_ + colL;
            if ((N_ % 32) == 0 || cG < N_) {
                float bb;
                if (E_ > 1) {
                    const float* cf = (q < 2) ? cf0 : cf1;
                    bb = 0.f;
                    #pragma unroll
                    for (int e = 0; e < E_; e++)
                        bb = fmaf(cf[e], __ldg(&bias[e * N_ + cG]), bb);
                } else {
                    bb = __ldg(&bias[cG]);
                }
                float v = tot[t][q] + bb;
                if (ACT_ == 1) v = elu1(v);
                C[r * ldc + cG] = v;
            }
        }
    }
}

// ============================================================
// mid kernel: mu/lv dual GEMM (K=523) -> z -> gate0 GEMM (K=299)
//             -> gate1 -> gate2 -> softmax -> coeff.
// 128 threads, 32 rows per block, grid = 128. All row-local.
// warps: wm16 = (wid&1)*16, wn32 = (wid>>1)*32
// ============================================================
#define K1T 17   // ceil(523/32)
#define K2T 10   // ceil(299/32)

__global__ __launch_bounds__(128) void mid_kernel(
    const float* __restrict__ x,   const float* __restrict__ h2,
    const float* __restrict__ wmu, const float* __restrict__ bmu,
    const float* __restrict__ wlv, const float* __restrict__ blv,
    const float* __restrict__ epsv, const float* __restrict__ cc,
    const float* __restrict__ gw0, const float* __restrict__ gb0,
    const float* __restrict__ gw1, const float* __restrict__ gb1,
    const float* __restrict__ gw2, const float* __restrict__ gb2,
    float* __restrict__ mu_out, float* __restrict__ lv_out,
    float* __restrict__ zout,   float* __restrict__ coeff)
{
    __shared__ float SMEM[9728];
    float (*As)[36]  = (float(*)[36]) (SMEM);          // 32*36  = 1152
    float (*Bs)[72]  = (float(*)[72]) (SMEM + 1152);   // 32*72  = 2304
    float (*zs)[33]  = (float(*)[33]) (SMEM + 3456);   // 32*33  = 1056
    float (*lvs)[33] = (float(*)[33]) (SMEM + 4512);   // 32*33  = 1056
    float (*g1s)[65] = (float(*)[65]) (SMEM + 5568);   // 32*65  = 2080
    float (*g2s)[65] = (float(*)[65]) (SMEM + 7648);   // 32*65  = 2080
    float (*w1s)[68] = (float(*)[68]) (SMEM);          // 64*68  = 4352 (overlays As/Bs/zs/lvs, phase 4 only)

    const int tid  = threadIdx.x;
    const int lane = tid & 31;
    const int wid  = tid >> 5;
    const int wm16 = (wid & 1) << 4;
    const int wn32 = (wid >> 1) << 5;
    const int gid  = lane >> 2;
    const int tg   = lane & 3;
    const int row0 = blockIdx.x * 32;

    // producers (32x32 A: 8/thr ; 32x64 B: 16/thr)
    const int am4 = tid >> 2;          // 0..31
    const int ak4 = (tid & 3) << 3;    // 0,8,16,24
    const int bk4 = tid >> 2;          // 0..31
    const int bn4 = (tid & 3) << 4;    // 0,16,32,48

    const int rL0 = wm16 + gid, rL1 = rL0 + 8;
    const int r0 = row0 + rL0, r1 = r0 + 8;

    // =============== phase 1: dual GEMM mu|lv, K=523 ===============
    float acc[4][4] = {};
    for (int tt = 0; tt < K1T; tt++) {
        const int kt = tt * 32;
        #pragma unroll
        for (int j = 0; j < 8; j++) {
            const int i = kt + ak4 + j;
            float v = 0.f;
            if (i < 523)
                v = (i < FRAME) ? __ldg(&x[(row0 + am4) * FRAME + i])
                                : __ldg(&h2[(row0 + am4) * HIDDEN + (i - FRAME)]);
            As[am4][ak4 + j] = tf32r(v);
        }
        {
            const int kg = kt + bk4;
            const bool kok = kg < 523;
            #pragma unroll
            for (int j = 0; j < 16; j++) {
                const int nl = bn4 + j;
                float v = 0.f;
                if (kok)
                    v = (nl < 32) ? __ldg(&wmu[kg * 32 + nl])
                                  : __ldg(&wlv[kg * 32 + (nl - 32)]);
                Bs[bk4][bn4 + j] = tf32r(v);
            }
        }
        __syncthreads();
        #pragma unroll
        for (int ks = 0; ks < 4; ks++) {
            const int kk = ks << 3;
            uint32_t a0 = __float_as_uint(As[rL0][kk + tg    ]);
            uint32_t a1 = __float_as_uint(As[rL1][kk + tg    ]);
            uint32_t a2 = __float_as_uint(As[rL0][kk + tg + 4]);
            uint32_t a3 = __float_as_uint(As[rL1][kk + tg + 4]);
            #pragma unroll
            for (int t = 0; t < 4; t++) {
                const int col = wn32 + (t << 3) + gid;
                uint32_t b0 = __float_as_uint(Bs[kk + tg    ][col]);
                uint32_t b1 = __float_as_uint(Bs[kk + tg + 4][col]);
                asm volatile(
                    "mma.sync.aligned.m16n8k8.row.col.f32.tf32.tf32.f32 "
                    "{%0,%1,%2,%3}, {%4,%5,%6,%7}, {%8,%9}, {%0,%1,%2,%3};\n"
                    : "+f"(acc[t][0]), "+f"(acc[t][1]),
                      "+f"(acc[t][2]), "+f"(acc[t][3])
                    : "r"(a0), "r"(a1), "r"(a2), "r"(a3), "r"(b0), "r"(b1));
            }
        }
        __syncthreads();
    }

    // epilogue 1: mu (wn32==0) kept in regs + written; lv -> smem + written
    float muv[4][4];
    #pragma unroll
    for (int t = 0; t < 4; t++) {
        #pragma unroll
        for (int q = 0; q < 4; q++) {
            const int r  = (q < 2) ? r0 : r1;
            const int rL = (q < 2) ? rL0 : rL1;
            const int colL = wn32 + (t << 3) + (tg << 1) + (q & 1);
            if (colL < 32) {
                const float m_ = acc[t][q] + __ldg(&bmu[colL]);
                mu_out[r * 32 + colL] = m_;
                muv[t][q] = m_;
            } else {
                const int cl = colL - 32;
                const float l_ = acc[t][q] + __ldg(&blv[cl]);
                lv_out[r * 32 + cl] = l_;
                lvs[rL][cl] = l_;
            }
        }
    }
    __syncthreads();

    // =============== phase 2: z = mu + eps*exp(0.5*lv) ===============
    if (wid < 2) {
        #pragma unroll
        for (int t = 0; t < 4; t++) {
            #pragma unroll
            for (int q = 0; q < 4; q++) {
                const int r  = (q < 2) ? r0 : r1;
                const int rL = (q < 2) ? rL0 : rL1;
                const int colL = (t << 3) + (tg << 1) + (q & 1);  // < 32
                const float zv = fmaf(__ldg(&epsv[r * 32 + colL]),
                                      expf(0.5f * lvs[rL][colL]), muv[t][q]);
                zs[rL][colL] = zv;
                zout[r * 32 + colL] = zv;
            }
        }
    }
    __syncthreads();

    // =============== phase 3: gate0 GEMM, K=299, N=64 ===============
    float ac2[4][4] = {};
    for (int tt = 0; tt < K2T; tt++) {
        const int kt = tt * 32;
        #pragma unroll
        for (int j = 0; j < 8; j++) {
            const int i = kt + ak4 + j;
            float v = 0.f;
            if (i < 32)          v = zs[am4][i];
            else if (i < IN0)    v = __ldg(&cc[(row0 + am4) * FRAME + (i - 32)]);
            As[am4][ak4 + j] = tf32r(v);
        }
        {
            const int kg = kt + bk4;
            const bool kok = kg < IN0;
            #pragma unroll
            for (int j = 0; j < 16; j++) {
                const int nl = bn4 + j;
                Bs[bk4][bn4 + j] = tf32r(kok ? __ldg(&gw0[kg * 64 + nl]) : 0.f);
            }
        }
        __syncthreads();
        #pragma unroll
        for (int ks = 0; ks < 4; ks++) {
            const int kk = ks << 3;
            uint32_t a0 = __float_as_uint(As[rL0][kk + tg    ]);
            uint32_t a1 = __float_as_uint(As[rL1][kk + tg    ]);
            uint32_t a2 = __float_as_uint(As[rL0][kk + tg + 4]);
            uint32_t a3 = __float_as_uint(As[rL1][kk + tg + 4]);
            #pragma unroll
            for (int t = 0; t < 4; t++) {
                const int col = wn32 + (t << 3) + gid;
                uint32_t b0 = __float_as_uint(Bs[kk + tg    ][col]);
                uint32_t b1 = __float_as_uint(Bs[kk + tg + 4][col]);
                asm volatile(
                    "mma.sync.aligned.m16n8k8.row.col.f32.tf32.tf32.f32 "
                    "{%0,%1,%2,%3}, {%4,%5,%6,%7}, {%8,%9}, {%0,%1,%2,%3};\n"
                    : "+f"(ac2[t][0]), "+f"(ac2[t][1]),
                      "+f"(ac2[t][2]), "+f"(ac2[t][3])
                    : "r"(a0), "r"(a1), "r"(a2), "r"(a3), "r"(b0), "r"(b1));
            }
        }
        __syncthreads();
    }
    #pragma unroll
    for (int t = 0; t < 4; t++) {
        #pragma unroll
        for (int q = 0; q < 4; q++) {
            const int rL = (q < 2) ? rL0 : rL1;
            const int colL = wn32 + (t << 3) + (tg << 1) + (q & 1);
            g1s[rL][colL] = elu1(ac2[t][q] + __ldg(&gb0[colL]));
        }
    }
    __syncthreads();

    // =============== phase 4: gate1 (64x64), w1 in smem ===============
    for (int i = tid; i < 64 * 64; i += 128)
        w1s[i >> 6][i & 63] = __ldg(&gw1[i]);
    __syncthreads();
    {
        const int row = tid >> 2;
        const int cs  = tid & 3;
        float a16[16];
        #pragma unroll
        for (int j = 0; j < 16; j++) a16[j] = __ldg(&gb1[cs + (j << 2)]);
        #pragma unroll
        for (int k = 0; k < 64; k++) {
            const float gv = g1s[row][k];
            #pragma unroll
            for (int j = 0; j < 16; j++)
                a16[j] = fmaf(gv, w1s[k][cs + (j << 2)], a16[j]);
        }
        #pragma unroll
        for (int j = 0; j < 16; j++)
            g2s[row][cs + (j << 2)] = elu1(a16[j]);
    }
    __syncthreads();

    // =============== phase 5: gate2 + softmax ===============
    if (tid < 32) {
        float lg[EXPERTS];
        #pragma unroll
        for (int e = 0; e < EXPERTS; e++) lg[e] = __ldg(&gb2[e]);
        #pragma unroll
        for (int k = 0; k < 64; k++) {
            const float gv = g2s[tid][k];
            #pragma unroll
            for (int e = 0; e < EXPERTS; e++)
                lg[e] = fmaf(gv, __ldg(&gw2[k * EXPERTS + e]), lg[e]);
        }
        float mx = lg[0];
        #pragma unroll
        for (int e = 1; e < EXPERTS; e++) mx = fmaxf(mx, lg[e]);
        float s = 0.f;
        #pragma unroll
        for (int e = 0; e < EXPERTS; e++) { lg[e] = expf(lg[e] - mx); s += lg[e]; }
        const float inv = 1.f / s;
        #pragma unroll
        for (int e = 0; e < EXPERTS; e++)
            coeff[(row0 + tid) * EXPERTS + e] = lg[e] * inv;
    }
}

// ---------------- launch ----------------
extern "C" void kernel_launch(void* const* d_in, const int* in_sizes, int n_in,
                              void* d_out, int out_size)
{
    const float* x       = (const float*)d_in[0];
    const float* c       = (const float*)d_in[1];
    const float* eps     = (const float*)d_in[2];
    const float* enc_w1  = (const float*)d_in[3];
    const float* enc_b1  = (const float*)d_in[4];
    const float* enc_w2  = (const float*)d_in[5];
    const float* enc_b2  = (const float*)d_in[6];
    const float* enc_wmu = (const float*)d_in[7];
    const float* enc_bmu = (const float*)d_in[8];
    const float* enc_wlv = (const float*)d_in[9];
    const float* enc_blv = (const float*)d_in[10];
    const float* gw0     = (const float*)d_in[11];
    const float* gb0     = (const float*)d_in[12];
    const float* gw1     = (const float*)d_in[13];
    const float* gb1     = (const float*)d_in[14];
    const float* gw2     = (const float*)d_in[15];
    const float* gb2     = (const float*)d_in[16];
    const float* w0      = (const float*)d_in[17];
    const float* b0      = (const float*)d_in[18];
    const float* w1      = (const float*)d_in[19];
    const float* b1      = (const float*)d_in[20];
    const float* w2      = (const float*)d_in[21];
    const float* b2      = (const float*)d_in[22];
    float* out = (float*)d_out;

    float *h1, *h2, *z, *coef, *d1, *d2;
    cudaGetSymbolAddress((void**)&h1,   g_h1);
    cudaGetSymbolAddress((void**)&h2,   g_h2);
    cudaGetSymbolAddress((void**)&z,    g_zbuf);
    cudaGetSymbolAddress((void**)&coef, g_coef);
    cudaGetSymbolAddress((void**)&d1,   g_d1);
    cudaGetSymbolAddress((void**)&d2,   g_d2);

    const dim3 blk(128);
    const dim3 gridH(HIDDEN / 32, BATCH / 64);              // (8, 64) = 512
    const dim3 gridO((OUTD + 31) / 32, BATCH / 64);         // (9, 64) = 576

    // encoder layer 1: h1 = elu([x, c] @ enc_w1 + b1)   K=534
    gemm128<HIDDEN, FRAME, 2*FRAME, 1, 1><<<gridH, blk>>>(
        x, FRAME, c, FRAME, nullptr, enc_w1, enc_b1, h1, HIDDEN);
    // encoder layer 2: h2 = elu([x, h1] @ enc_w2 + b2)  K=523
    gemm128<HIDDEN, FRAME, FRAME+HIDDEN, 1, 1><<<gridH, blk>>>(
        x, FRAME, h1, HIDDEN, nullptr, enc_w2, enc_b2, h2, HIDDEN);
    // mid: mu/lv + z + gate0 + gate1 + gate2 + softmax
    mid_kernel<<<BATCH / 32, blk>>>(
        x, h2, enc_wmu, enc_bmu, enc_wlv, enc_blv, eps, c,
        gw0, gb0, gw1, gb1, gw2, gb2,
        out + OFF_MU, out + OFF_LV, z, coef);
    // MoE decoder layer 0: per-expert K=299 (padded to 320)
    gemm128<HIDDEN, LATENT, IN0, EXPERTS, 1><<<gridH, blk>>>(
        z, LATENT, c, FRAME, coef, w0, b0, d1, HIDDEN);
    // MoE decoder layer 1: per-expert K=288 (tile-exact)
    gemm128<HIDDEN, LATENT, IN1, EXPERTS, 1><<<gridH, blk>>>(
        z, LATENT, d1, HIDDEN, coef, w1, b1, d2, HIDDEN);
    // MoE decoder layer 2 (no act): N=267
    gemm128<OUTD, LATENT, IN1, EXPERTS, 0><<<gridO, blk>>>(
        z, LATENT, d2, HIDDEN, coef, w2, b2, out, OUTD);
}

// round 5
// speedup vs baseline: 1.7611x; 1.7611x over previous
#include <cuda_runtime.h>
#include <cstdint>

// ---------------- problem constants ----------------
#define BATCH   4096
#define FRAME   267
#define LATENT  32
#define HIDDEN  256
#define GATE_H  64
#define EXPERTS 6
#define IN0     (LATENT + FRAME)    // 299
#define IN1     (LATENT + HIDDEN)   // 288
#define OUTD    FRAME               // 267

#define OFF_MU  (BATCH * OUTD)
#define OFF_LV  (OFF_MU + BATCH * LATENT)

// ---------------- scratch (allocation-free) ----------------
__device__ float g_h1[BATCH * HIDDEN];
__device__ float g_h2[BATCH * HIDDEN];
__device__ float g_zbuf[BATCH * LATENT];
__device__ float g_coef[BATCH * EXPERTS];
__device__ float g_d1[BATCH * HIDDEN];
__device__ float g_d2[BATCH * HIDDEN];

__device__ __forceinline__ float elu1(float x) { return x > 0.f ? x : expm1f(x); }

__device__ __forceinline__ float tf32r(float x) {
    float y;
    asm("cvt.rna.tf32.f32 %0, %1;" : "=f"(y) : "f"(x));
    return y;
}

// ============================================================
// R2-proven tf32 mma GEMM (exact smem layout + consumer), plus
// register prefetch of the next k-tile overlapped with MMA.
//   C[m,n] = act( Afold[m,:] @ Wflat[:,n] + biasblend )
//   Afold[m, e*DIN+i] = (i<K0 ? A0[m,i] : A1[m,i-K0]) * (E>1 ? coeff[m,e] : 1)
// Tile 64x64x32, 256 threads, 8 warps (4m x 2n), warp tile m16n32.
// ============================================================
#define BK 32

template<int N_, int K0_, int DIN_, int E_, int ACT_>
__global__ __launch_bounds__(256) void mma_gemm(
    const float* __restrict__ A0, int lda0,
    const float* __restrict__ A1, int lda1,
    const float* __restrict__ coeff,
    const float* __restrict__ W, const float* __restrict__ bias,
    float* __restrict__ C, int ldc)
{
    constexpr int Ktot = E_ * DIN_;
    __shared__ float As[64][36];   // [m][k] — consumer bank (m*4+k)%32 conflict-free
    __shared__ float Bs[32][72];   // [k][n] — consumer bank (k*8+n)%32 conflict-free

    const int tid  = threadIdx.x;
    const int lane = tid & 31;
    const int wid  = tid >> 5;
    const int wm16 = (wid >> 1) << 4;   // 0,16,32,48
    const int wn32 = (wid & 1) << 5;    // 0,32
    const int gid  = lane >> 2;
    const int tg   = lane & 3;

    const int bm_ = blockIdx.y * 64;
    const int bn_ = blockIdx.x * 64;

    // producer mappings (R2)
    const int amL = tid >> 3;            // 0..31 (two halves: +0,+32)
    const int akq = (tid & 7) << 2;      // 0..28
    const int bkL = tid >> 4;            // 0..15 (two halves: +0,+16)
    const int bnb = (tid & 15) << 2;     // 0..60

    float avv[2][4], bvv[2][4];

    auto ldgA = [&](int kt, float a[2][4]) {
        #pragma unroll
        for (int half = 0; half < 2; half++) {
            const int m = bm_ + amL + half * 32;
            #pragma unroll
            for (int j = 0; j < 4; j++) {
                const int ig = kt + akq + j;
                float val = 0.f;
                if ((Ktot % BK == 0) || ig < Ktot) {
                    int e, i;
                    if (E_ == 1) { e = 0; i = ig; }
                    else { e = ig / DIN_; i = ig - e * DIN_; }
                    val = (i < K0_) ? __ldg(&A0[m * lda0 + i])
                                    : __ldg(&A1[m * lda1 + (i - K0_)]);
                    if (E_ > 1) val *= __ldg(&coeff[m * E_ + e]);
                }
                a[half][j] = val;
            }
        }
    };
    auto ldgB = [&](int kt, float b[2][4]) {
        #pragma unroll
        for (int half = 0; half < 2; half++) {
            const int kg = kt + bkL + half * 16;
            const bool kok = (Ktot % BK == 0) || (kg < Ktot);
            #pragma unroll
            for (int j = 0; j < 4; j++) {
                const int n = bn_ + bnb + j;
                float val = 0.f;
                if (kok && ((N_ % 64) == 0 || n < N_))
                    val = __ldg(&W[(size_t)kg * N_ + n]);
                b[half][j] = val;
            }
        }
    };
    auto sts = [&](float a[2][4], float b[2][4]) {
        #pragma unroll
        for (int half = 0; half < 2; half++) {
            const int mL = amL + half * 32;
            #pragma unroll
            for (int j = 0; j < 4; j++)
                As[mL][akq + j] = tf32r(a[half][j]);
        }
        #pragma unroll
        for (int half = 0; half < 2; half++) {
            const int kL = bkL + half * 16;
            #pragma unroll
            for (int j = 0; j < 4; j++)
                Bs[kL][bnb + j] = tf32r(b[half][j]);
        }
    };

    float acc[4][4] = {};

    ldgA(0, avv); ldgB(0, bvv);
    for (int kt = 0; kt < Ktot; kt += BK) {
        sts(avv, bvv);
        __syncthreads();

        float avn[2][4], bvn[2][4];
        const bool more = (kt + BK < Ktot);
        if (more) { ldgA(kt + BK, avn); ldgB(kt + BK, bvn); }

        #pragma unroll
        for (int ks = 0; ks < 4; ks++) {
            const int kk = ks << 3;
            uint32_t a0 = __float_as_uint(As[wm16 + gid    ][kk + tg    ]);
            uint32_t a1 = __float_as_uint(As[wm16 + gid + 8][kk + tg    ]);
            uint32_t a2 = __float_as_uint(As[wm16 + gid    ][kk + tg + 4]);
            uint32_t a3 = __float_as_uint(As[wm16 + gid + 8][kk + tg + 4]);
            #pragma unroll
            for (int t = 0; t < 4; t++) {
                const int col = wn32 + (t << 3) + gid;
                uint32_t b0 = __float_as_uint(Bs[kk + tg    ][col]);
                uint32_t b1 = __float_as_uint(Bs[kk + tg + 4][col]);
                asm volatile(
                    "mma.sync.aligned.m16n8k8.row.col.f32.tf32.tf32.f32 "
                    "{%0,%1,%2,%3}, {%4,%5,%6,%7}, {%8,%9}, {%0,%1,%2,%3};\n"
                    : "+f"(acc[t][0]), "+f"(acc[t][1]),
                      "+f"(acc[t][2]), "+f"(acc[t][3])
                    : "r"(a0), "r"(a1), "r"(a2), "r"(a3), "r"(b0), "r"(b1));
            }
        }
        __syncthreads();

        if (more) {
            #pragma unroll
            for (int h = 0; h < 2; h++)
                #pragma unroll
                for (int j = 0; j < 4; j++) {
                    avv[h][j] = avn[h][j];
                    bvv[h][j] = bvn[h][j];
                }
        }
    }

    // ---- epilogue (R2) ----
    const int r0 = bm_ + wm16 + gid;
    const int r1 = r0 + 8;
    float cf0[E_ > 1 ? E_ : 1], cf1[E_ > 1 ? E_ : 1];
    if (E_ > 1) {
        #pragma unroll
        for (int e = 0; e < E_; e++) {
            cf0[e] = coeff[r0 * E_ + e];
            cf1[e] = coeff[r1 * E_ + e];
        }
    }

    #pragma unroll
    for (int t = 0; t < 4; t++) {
        #pragma unroll
        for (int q = 0; q < 4; q++) {
            const int r  = (q < 2) ? r0 : r1;
            const int colL = wn32 + (t << 3) + (tg << 1) + (q & 1);
            const int cG = bn_ + colL;
            if ((N_ % 64) == 0 || cG < N_) {
                float bb;
                if (E_ > 1) {
                    const float* cf = (q < 2) ? cf0 : cf1;
                    bb = 0.f;
                    #pragma unroll
                    for (int e = 0; e < E_; e++)
                        bb = fmaf(cf[e], __ldg(&bias[e * N_ + cG]), bb);
                } else {
                    bb = __ldg(&bias[cG]);
                }
                float v = acc[t][q] + bb;
                if (ACT_ == 1) v = elu1(v);
                C[r * ldc + cG] = v;
            }
        }
    }
}

// ============================================================
// mid kernel (verbatim from R4, numerically verified):
// mu/lv dual GEMM (K=523) -> z -> gate0 GEMM (K=299)
// -> gate1 -> gate2 -> softmax -> coeff.
// 128 threads, 32 rows per block, grid = 128.
// ============================================================
#define K1T 17   // ceil(523/32)
#define K2T 10   // ceil(299/32)

__global__ __launch_bounds__(128) void mid_kernel(
    const float* __restrict__ x,   const float* __restrict__ h2,
    const float* __restrict__ wmu, const float* __restrict__ bmu,
    const float* __restrict__ wlv, const float* __restrict__ blv,
    const float* __restrict__ epsv, const float* __restrict__ cc,
    const float* __restrict__ gw0, const float* __restrict__ gb0,
    const float* __restrict__ gw1, const float* __restrict__ gb1,
    const float* __restrict__ gw2, const float* __restrict__ gb2,
    float* __restrict__ mu_out, float* __restrict__ lv_out,
    float* __restrict__ zout,   float* __restrict__ coeff)
{
    __shared__ float SMEM[9728];
    float (*As)[36]  = (float(*)[36]) (SMEM);          // 32*36
    float (*Bs)[72]  = (float(*)[72]) (SMEM + 1152);   // 32*72
    float (*zs)[33]  = (float(*)[33]) (SMEM + 3456);
    float (*lvs)[33] = (float(*)[33]) (SMEM + 4512);
    float (*g1s)[65] = (float(*)[65]) (SMEM + 5568);
    float (*g2s)[65] = (float(*)[65]) (SMEM + 7648);
    float (*w1s)[68] = (float(*)[68]) (SMEM);          // phase-4 overlay

    const int tid  = threadIdx.x;
    const int lane = tid & 31;
    const int wid  = tid >> 5;
    const int wm16 = (wid & 1) << 4;
    const int wn32 = (wid >> 1) << 5;
    const int gid  = lane >> 2;
    const int tg   = lane & 3;
    const int row0 = blockIdx.x * 32;

    const int am4 = tid >> 2;          // 0..31
    const int ak4 = (tid & 3) << 3;    // 0,8,16,24
    const int bk4 = tid >> 2;          // 0..31
    const int bn4 = (tid & 3) << 4;    // 0,16,32,48

    const int rL0 = wm16 + gid, rL1 = rL0 + 8;
    const int r0 = row0 + rL0, r1 = r0 + 8;

    // phase 1: dual GEMM mu|lv, K=523
    float acc[4][4] = {};
    for (int tt = 0; tt < K1T; tt++) {
        const int kt = tt * 32;
        #pragma unroll
        for (int j = 0; j < 8; j++) {
            const int i = kt + ak4 + j;
            float v = 0.f;
            if (i < 523)
                v = (i < FRAME) ? __ldg(&x[(row0 + am4) * FRAME + i])
                                : __ldg(&h2[(row0 + am4) * HIDDEN + (i - FRAME)]);
            As[am4][ak4 + j] = tf32r(v);
        }
        {
            const int kg = kt + bk4;
            const bool kok = kg < 523;
            #pragma unroll
            for (int j = 0; j < 16; j++) {
                const int nl = bn4 + j;
                float v = 0.f;
                if (kok)
                    v = (nl < 32) ? __ldg(&wmu[kg * 32 + nl])
                                  : __ldg(&wlv[kg * 32 + (nl - 32)]);
                Bs[bk4][bn4 + j] = tf32r(v);
            }
        }
        __syncthreads();
        #pragma unroll
        for (int ks = 0; ks < 4; ks++) {
            const int kk = ks << 3;
            uint32_t a0 = __float_as_uint(As[rL0][kk + tg    ]);
            uint32_t a1 = __float_as_uint(As[rL1][kk + tg    ]);
            uint32_t a2 = __float_as_uint(As[rL0][kk + tg + 4]);
            uint32_t a3 = __float_as_uint(As[rL1][kk + tg + 4]);
            #pragma unroll
            for (int t = 0; t < 4; t++) {
                const int col = wn32 + (t << 3) + gid;
                uint32_t b0 = __float_as_uint(Bs[kk + tg    ][col]);
                uint32_t b1 = __float_as_uint(Bs[kk + tg + 4][col]);
                asm volatile(
                    "mma.sync.aligned.m16n8k8.row.col.f32.tf32.tf32.f32 "
                    "{%0,%1,%2,%3}, {%4,%5,%6,%7}, {%8,%9}, {%0,%1,%2,%3};\n"
                    : "+f"(acc[t][0]), "+f"(acc[t][1]),
                      "+f"(acc[t][2]), "+f"(acc[t][3])
                    : "r"(a0), "r"(a1), "r"(a2), "r"(a3), "r"(b0), "r"(b1));
            }
        }
        __syncthreads();
    }

    float muv[4][4];
    #pragma unroll
    for (int t = 0; t < 4; t++) {
        #pragma unroll
        for (int q = 0; q < 4; q++) {
            const int r  = (q < 2) ? r0 : r1;
            const int rL = (q < 2) ? rL0 : rL1;
            const int colL = wn32 + (t << 3) + (tg << 1) + (q & 1);
            if (colL < 32) {
                const float m_ = acc[t][q] + __ldg(&bmu[colL]);
                mu_out[r * 32 + colL] = m_;
                muv[t][q] = m_;
            } else {
                const int cl = colL - 32;
                const float l_ = acc[t][q] + __ldg(&blv[cl]);
                lv_out[r * 32 + cl] = l_;
                lvs[rL][cl] = l_;
            }
        }
    }
    __syncthreads();

    // phase 2: z = mu + eps*exp(0.5*lv)
    if (wid < 2) {
        #pragma unroll
        for (int t = 0; t < 4; t++) {
            #pragma unroll
            for (int q = 0; q < 4; q++) {
                const int r  = (q < 2) ? r0 : r1;
                const int rL = (q < 2) ? rL0 : rL1;
                const int colL = (t << 3) + (tg << 1) + (q & 1);
                const float zv = fmaf(__ldg(&epsv[r * 32 + colL]),
                                      expf(0.5f * lvs[rL][colL]), muv[t][q]);
                zs[rL][colL] = zv;
                zout[r * 32 + colL] = zv;
            }
        }
    }
    __syncthreads();

    // phase 3: gate0 GEMM, K=299, N=64
    float ac2[4][4] = {};
    for (int tt = 0; tt < K2T; tt++) {
        const int kt = tt * 32;
        #pragma unroll
        for (int j = 0; j < 8; j++) {
            const int i = kt + ak4 + j;
            float v = 0.f;
            if (i < 32)          v = zs[am4][i];
            else if (i < IN0)    v = __ldg(&cc[(row0 + am4) * FRAME + (i - 32)]);
            As[am4][ak4 + j] = tf32r(v);
        }
        {
            const int kg = kt + bk4;
            const bool kok = kg < IN0;
            #pragma unroll
            for (int j = 0; j < 16; j++) {
                const int nl = bn4 + j;
                Bs[bk4][bn4 + j] = tf32r(kok ? __ldg(&gw0[kg * 64 + nl]) : 0.f);
            }
        }
        __syncthreads();
        #pragma unroll
        for (int ks = 0; ks < 4; ks++) {
            const int kk = ks << 3;
            uint32_t a0 = __float_as_uint(As[rL0][kk + tg    ]);
            uint32_t a1 = __float_as_uint(As[rL1][kk + tg    ]);
            uint32_t a2 = __float_as_uint(As[rL0][kk + tg + 4]);
            uint32_t a3 = __float_as_uint(As[rL1][kk + tg + 4]);
            #pragma unroll
            for (int t = 0; t < 4; t++) {
                const int col = wn32 + (t << 3) + gid;
                uint32_t b0 = __float_as_uint(Bs[kk + tg    ][col]);
                uint32_t b1 = __float_as_uint(Bs[kk + tg + 4][col]);
                asm volatile(
                    "mma.sync.aligned.m16n8k8.row.col.f32.tf32.tf32.f32 "
                    "{%0,%1,%2,%3}, {%4,%5,%6,%7}, {%8,%9}, {%0,%1,%2,%3};\n"
                    : "+f"(ac2[t][0]), "+f"(ac2[t][1]),
                      "+f"(ac2[t][2]), "+f"(ac2[t][3])
                    : "r"(a0), "r"(a1), "r"(a2), "r"(a3), "r"(b0), "r"(b1));
            }
        }
        __syncthreads();
    }
    #pragma unroll
    for (int t = 0; t < 4; t++) {
        #pragma unroll
        for (int q = 0; q < 4; q++) {
            const int rL = (q < 2) ? rL0 : rL1;
            const int colL = wn32 + (t << 3) + (tg << 1) + (q & 1);
            g1s[rL][colL] = elu1(ac2[t][q] + __ldg(&gb0[colL]));
        }
    }
    __syncthreads();

    // phase 4: gate1 (64x64), w1 in smem
    for (int i = tid; i < 64 * 64; i += 128)
        w1s[i >> 6][i & 63] = __ldg(&gw1[i]);
    __syncthreads();
    {
        const int row = tid >> 2;
        const int cs  = tid & 3;
        float a16[16];
        #pragma unroll
        for (int j = 0; j < 16; j++) a16[j] = __ldg(&gb1[cs + (j << 2)]);
        #pragma unroll
        for (int k = 0; k < 64; k++) {
            const float gv = g1s[row][k];
            #pragma unroll
            for (int j = 0; j < 16; j++)
                a16[j] = fmaf(gv, w1s[k][cs + (j << 2)], a16[j]);
        }
        #pragma unroll
        for (int j = 0; j < 16; j++)
            g2s[row][cs + (j << 2)] = elu1(a16[j]);
    }
    __syncthreads();

    // phase 5: gate2 + softmax
    if (tid < 32) {
        float lg[EXPERTS];
        #pragma unroll
        for (int e = 0; e < EXPERTS; e++) lg[e] = __ldg(&gb2[e]);
        #pragma unroll
        for (int k = 0; k < 64; k++) {
            const float gv = g2s[tid][k];
            #pragma unroll
            for (int e = 0; e < EXPERTS; e++)
                lg[e] = fmaf(gv, __ldg(&gw2[k * EXPERTS + e]), lg[e]);
        }
        float mx = lg[0];
        #pragma unroll
        for (int e = 1; e < EXPERTS; e++) mx = fmaxf(mx, lg[e]);
        float s = 0.f;
        #pragma unroll
        for (int e = 0; e < EXPERTS; e++) { lg[e] = expf(lg[e] - mx); s += lg[e]; }
        const float inv = 1.f / s;
        #pragma unroll
        for (int e = 0; e < EXPERTS; e++)
            coeff[(row0 + tid) * EXPERTS + e] = lg[e] * inv;
    }
}

// ---------------- launch ----------------
extern "C" void kernel_launch(void* const* d_in, const int* in_sizes, int n_in,
                              void* d_out, int out_size)
{
    const float* x       = (const float*)d_in[0];
    const float* c       = (const float*)d_in[1];
    const float* eps     = (const float*)d_in[2];
    const float* enc_w1  = (const float*)d_in[3];
    const float* enc_b1  = (const float*)d_in[4];
    const float* enc_w2  = (const float*)d_in[5];
    const float* enc_b2  = (const float*)d_in[6];
    const float* enc_wmu = (const float*)d_in[7];
    const float* enc_bmu = (const float*)d_in[8];
    const float* enc_wlv = (const float*)d_in[9];
    const float* enc_blv = (const float*)d_in[10];
    const float* gw0     = (const float*)d_in[11];
    const float* gb0     = (const float*)d_in[12];
    const float* gw1     = (const float*)d_in[13];
    const float* gb1     = (const float*)d_in[14];
    const float* gw2     = (const float*)d_in[15];
    const float* gb2     = (const float*)d_in[16];
    const float* w0      = (const float*)d_in[17];
    const float* b0      = (const float*)d_in[18];
    const float* w1      = (const float*)d_in[19];
    const float* b1      = (const float*)d_in[20];
    const float* w2      = (const float*)d_in[21];
    const float* b2      = (const float*)d_in[22];
    float* out = (float*)d_out;

    float *h1, *h2, *z, *coef, *d1, *d2;
    cudaGetSymbolAddress((void**)&h1,   g_h1);
    cudaGetSymbolAddress((void**)&h2,   g_h2);
    cudaGetSymbolAddress((void**)&z,    g_zbuf);
    cudaGetSymbolAddress((void**)&coef, g_coef);
    cudaGetSymbolAddress((void**)&d1,   g_d1);
    cudaGetSymbolAddress((void**)&d2,   g_d2);

    const dim3 blk(256);
    const dim3 gridH(HIDDEN / 64, BATCH / 64);              // (4, 64)
    const dim3 gridO((OUTD + 63) / 64, BATCH / 64);         // (5, 64)

    // encoder layer 1: h1 = elu([x, c] @ enc_w1 + b1)   K=534
    mma_gemm<HIDDEN, FRAME, 2*FRAME, 1, 1><<<gridH, blk>>>(
        x, FRAME, c, FRAME, nullptr, enc_w1, enc_b1, h1, HIDDEN);
    // encoder layer 2: h2 = elu([x, h1] @ enc_w2 + b2)  K=523
    mma_gemm<HIDDEN, FRAME, FRAME+HIDDEN, 1, 1><<<gridH, blk>>>(
        x, FRAME, h1, HIDDEN, nullptr, enc_w2, enc_b2, h2, HIDDEN);
    // mid: mu/lv + z + gate0 + gate1 + gate2 + softmax
    mid_kernel<<<BATCH / 32, dim3(128)>>>(
        x, h2, enc_wmu, enc_bmu, enc_wlv, enc_blv, eps, c,
        gw0, gb0, gw1, gb1, gw2, gb2,
        out + OFF_MU, out + OFF_LV, z, coef);
    // MoE decoder layer 0: Ktot = 6*299 = 1794
    mma_gemm<HIDDEN, LATENT, IN0, EXPERTS, 1><<<gridH, blk>>>(
        z, LATENT, c, FRAME, coef, w0, b0, d1, HIDDEN);
    // MoE decoder layer 1: Ktot = 6*288 = 1728
    mma_gemm<HIDDEN, LATENT, IN1, EXPERTS, 1><<<gridH, blk>>>(
        z, LATENT, d1, HIDDEN, coef, w1, b1, d2, HIDDEN);
    // MoE decoder layer 2 (no act): N=267, Ktot=1728
    mma_gemm<OUTD, LATENT, IN1, EXPERTS, 0><<<gridO, blk>>>(
        z, LATENT, d2, HIDDEN, coef, w2, b2, out, OUTD);
}

// round 7
// speedup vs baseline: 1.8536x; 1.0525x over previous
#include <cuda_runtime.h>
#include <cstdint>

// ---------------- problem constants ----------------
#define BATCH   4096
#define FRAME   267
#define LATENT  32
#define HIDDEN  256
#define GATE_H  64
#define EXPERTS 6
#define IN0     (LATENT + FRAME)    // 299
#define IN1     (LATENT + HIDDEN)   // 288
#define OUTD    FRAME               // 267

#define OFF_MU  (BATCH * OUTD)
#define OFF_LV  (OFF_MU + BATCH * LATENT)

// ---------------- scratch (allocation-free) ----------------
__device__ float g_h1[BATCH * HIDDEN];
__device__ float g_h2[BATCH * HIDDEN];
__device__ float g_zbuf[BATCH * LATENT];
__device__ float g_coef[BATCH * EXPERTS];
__device__ float g_d1[BATCH * HIDDEN];
__device__ float g_d2[BATCH * HIDDEN];

__device__ __forceinline__ float elu1(float x) { return x > 0.f ? x : expm1f(x); }

__device__ __forceinline__ float tf32r(float x) {
    float y;
    asm("cvt.rna.tf32.f32 %0, %1;" : "=f"(y) : "f"(x));
    return y;
}

// ============================================================
// R5-proven tf32 mma GEMM. ONE change vs R5: the A loader's
// per-element integer division (ig / DIN) is replaced by
// incremental (expert, local index) tracking advanced once per
// k-tile. B loader, guards, smem layout, consumer, epilogue are
// identical to the R5 kernel that passed at 477us.
//   C[m,n] = act( Afold[m,:] @ Wflat[:,n] + biasblend )
//   Afold[m, e*DIN+i] = (i<K0 ? A0[m,i] : A1[m,i-K0]) * (E>1 ? coeff[m,e] : 1)
// Tile 64x64x32, 256 threads, 8 warps (4m x 2n), warp tile m16n32.
// ============================================================
#define BK 32

template<int N_, int K0_, int DIN_, int E_, int ACT_>
__global__ __launch_bounds__(256) void mma_gemm(
    const float* __restrict__ A0, int lda0,
    const float* __restrict__ A1, int lda1,
    const float* __restrict__ coeff,
    const float* __restrict__ W, const float* __restrict__ bias,
    float* __restrict__ C, int ldc)
{
    constexpr int Ktot = E_ * DIN_;
    __shared__ float As[64][36];   // [m][k] — consumer bank (m*4+k)%32 conflict-free
    __shared__ float Bs[32][72];   // [k][n] — consumer bank (k*8+n)%32 conflict-free

    const int tid  = threadIdx.x;
    const int lane = tid & 31;
    const int wid  = tid >> 5;
    const int wm16 = (wid >> 1) << 4;   // 0,16,32,48
    const int wn32 = (wid & 1) << 5;    // 0,32
    const int gid  = lane >> 2;
    const int tg   = lane & 3;

    const int bm_ = blockIdx.y * 64;
    const int bn_ = blockIdx.x * 64;

    // producer mappings (R2/R5)
    const int amL = tid >> 3;            // 0..31 (two halves: +0,+32)
    const int akq = (tid & 7) << 2;      // 0..28
    const int bkL = tid >> 4;            // 0..15 (two halves: +0,+16)
    const int bnb = (tid & 15) << 2;     // 0..60

    // incremental decomposition of (kt + akq) into (eA, iA): iA in [0, DIN)
    int eA = 0, iA = akq;

    float avv[2][4], bvv[2][4];

    auto ldgA = [&](int kt, float a[2][4]) {
        if (E_ == 1) {
            #pragma unroll
            for (int half = 0; half < 2; half++) {
                const int m = bm_ + amL + half * 32;
                #pragma unroll
                for (int j = 0; j < 4; j++) {
                    const int ig = kt + akq + j;
                    float val = 0.f;
                    if ((Ktot % BK == 0) || ig < Ktot)
                        val = (ig < K0_) ? __ldg(&A0[m * lda0 + ig])
                                         : __ldg(&A1[m * lda1 + (ig - K0_)]);
                    a[half][j] = val;
                }
            }
        } else {
            const int eC  = (eA < E_)     ? eA     : (E_ - 1);
            const int eC1 = (eA + 1 < E_) ? eA + 1 : (E_ - 1);
            #pragma unroll
            for (int half = 0; half < 2; half++) {
                const int m = bm_ + amL + half * 32;
                const float cf0v = __ldg(&coeff[m * E_ + eC]);
                const float cf1v = __ldg(&coeff[m * E_ + eC1]);
                #pragma unroll
                for (int j = 0; j < 4; j++) {
                    int i = iA + j;
                    const bool wrap = (i >= DIN_);
                    if (wrap) i -= DIN_;
                    const int ig = kt + akq + j;
                    float val = 0.f;
                    if ((Ktot % BK == 0) || ig < Ktot) {
                        val = (i < K0_) ? __ldg(&A0[m * lda0 + i])
                                        : __ldg(&A1[m * lda1 + (i - K0_)]);
                        val *= wrap ? cf1v : cf0v;
                    }
                    a[half][j] = val;
                }
            }
            // advance state to the next k-tile (call order is strictly t, t+1, ...)
            iA += 32;
            if (iA >= DIN_) { eA++; iA -= DIN_; }
        }
    };
    auto ldgB = [&](int kt, float b[2][4]) {
        #pragma unroll
        for (int half = 0; half < 2; half++) {
            const int kg = kt + bkL + half * 16;
            const bool kok = (Ktot % BK == 0) || (kg < Ktot);
            #pragma unroll
            for (int j = 0; j < 4; j++) {
                const int n = bn_ + bnb + j;
                float val = 0.f;
                if (kok && ((N_ % 64) == 0 || n < N_))
                    val = __ldg(&W[(size_t)kg * N_ + n]);
                b[half][j] = val;
            }
        }
    };
    auto sts = [&](float a[2][4], float b[2][4]) {
        #pragma unroll
        for (int half = 0; half < 2; half++) {
            const int mL = amL + half * 32;
            #pragma unroll
            for (int j = 0; j < 4; j++)
                As[mL][akq + j] = tf32r(a[half][j]);
        }
        #pragma unroll
        for (int half = 0; half < 2; half++) {
            const int kL = bkL + half * 16;
            #pragma unroll
            for (int j = 0; j < 4; j++)
                Bs[kL][bnb + j] = tf32r(b[half][j]);
        }
    };

    float acc[4][4] = {};

    ldgA(0, avv); ldgB(0, bvv);
    for (int kt = 0; kt < Ktot; kt += BK) {
        sts(avv, bvv);
        __syncthreads();

        float avn[2][4], bvn[2][4];
        const bool more = (kt + BK < Ktot);
        if (more) { ldgA(kt + BK, avn); ldgB(kt + BK, bvn); }

        #pragma unroll
        for (int ks = 0; ks < 4; ks++) {
            const int kk = ks << 3;
            uint32_t a0 = __float_as_uint(As[wm16 + gid    ][kk + tg    ]);
            uint32_t a1 = __float_as_uint(As[wm16 + gid + 8][kk + tg    ]);
            uint32_t a2 = __float_as_uint(As[wm16 + gid    ][kk + tg + 4]);
            uint32_t a3 = __float_as_uint(As[wm16 + gid + 8][kk + tg + 4]);
            #pragma unroll
            for (int t = 0; t < 4; t++) {
                const int col = wn32 + (t << 3) + gid;
                uint32_t b0 = __float_as_uint(Bs[kk + tg    ][col]);
                uint32_t b1 = __float_as_uint(Bs[kk + tg + 4][col]);
                asm volatile(
                    "mma.sync.aligned.m16n8k8.row.col.f32.tf32.tf32.f32 "
                    "{%0,%1,%2,%3}, {%4,%5,%6,%7}, {%8,%9}, {%0,%1,%2,%3};\n"
                    : "+f"(acc[t][0]), "+f"(acc[t][1]),
                      "+f"(acc[t][2]), "+f"(acc[t][3])
                    : "r"(a0), "r"(a1), "r"(a2), "r"(a3), "r"(b0), "r"(b1));
            }
        }
        __syncthreads();

        if (more) {
            #pragma unroll
            for (int h = 0; h < 2; h++)
                #pragma unroll
                for (int j = 0; j < 4; j++) {
                    avv[h][j] = avn[h][j];
                    bvv[h][j] = bvn[h][j];
                }
        }
    }

    // ---- epilogue (R5) ----
    const int r0 = bm_ + wm16 + gid;
    const int r1 = r0 + 8;
    float cf0[E_ > 1 ? E_ : 1], cf1[E_ > 1 ? E_ : 1];
    if (E_ > 1) {
        #pragma unroll
        for (int e = 0; e < E_; e++) {
            cf0[e] = coeff[r0 * E_ + e];
            cf1[e] = coeff[r1 * E_ + e];
        }
    }

    #pragma unroll
    for (int t = 0; t < 4; t++) {
        #pragma unroll
        for (int q = 0; q < 4; q++) {
            const int r  = (q < 2) ? r0 : r1;
            const int colL = wn32 + (t << 3) + (tg << 1) + (q & 1);
            const int cG = bn_ + colL;
            if ((N_ % 64) == 0 || cG < N_) {
                float bb;
                if (E_ > 1) {
                    const float* cf = (q < 2) ? cf0 : cf1;
                    bb = 0.f;
                    #pragma unroll
                    for (int e = 0; e < E_; e++)
                        bb = fmaf(cf[e], __ldg(&bias[e * N_ + cG]), bb);
                } else {
                    bb = __ldg(&bias[cG]);
                }
                float v = acc[t][q] + bb;
                if (ACT_ == 1) v = elu1(v);
                C[r * ldc + cG] = v;
            }
        }
    }
}

// ============================================================
// mid kernel (verbatim from R5, passing):
// mu/lv dual GEMM (K=523) -> z -> gate0 GEMM (K=299)
// -> gate1 -> gate2 -> softmax -> coeff.
// 128 threads, 32 rows per block, grid = 128.
// ============================================================
#define K1T 17   // ceil(523/32)
#define K2T 10   // ceil(299/32)

__global__ __launch_bounds__(128) void mid_kernel(
    const float* __restrict__ x,   const float* __restrict__ h2,
    const float* __restrict__ wmu, const float* __restrict__ bmu,
    const float* __restrict__ wlv, const float* __restrict__ blv,
    const float* __restrict__ epsv, const float* __restrict__ cc,
    const float* __restrict__ gw0, const float* __restrict__ gb0,
    const float* __restrict__ gw1, const float* __restrict__ gb1,
    const float* __restrict__ gw2, const float* __restrict__ gb2,
    float* __restrict__ mu_out, float* __restrict__ lv_out,
    float* __restrict__ zout,   float* __restrict__ coeff)
{
    __shared__ float SMEM[9728];
    float (*As)[36]  = (float(*)[36]) (SMEM);          // 32*36
    float (*Bs)[72]  = (float(*)[72]) (SMEM + 1152);   // 32*72
    float (*zs)[33]  = (float(*)[33]) (SMEM + 3456);
    float (*lvs)[33] = (float(*)[33]) (SMEM + 4512);
    float (*g1s)[65] = (float(*)[65]) (SMEM + 5568);
    float (*g2s)[65] = (float(*)[65]) (SMEM + 7648);
    float (*w1s)[68] = (float(*)[68]) (SMEM);          // phase-4 overlay

    const int tid  = threadIdx.x;
    const int lane = tid & 31;
    const int wid  = tid >> 5;
    const int wm16 = (wid & 1) << 4;
    const int wn32 = (wid >> 1) << 5;
    const int gid  = lane >> 2;
    const int tg   = lane & 3;
    const int row0 = blockIdx.x * 32;

    const int am4 = tid >> 2;          // 0..31
    const int ak4 = (tid & 3) << 3;    // 0,8,16,24
    const int bk4 = tid >> 2;          // 0..31
    const int bn4 = (tid & 3) << 4;    // 0,16,32,48

    const int rL0 = wm16 + gid, rL1 = rL0 + 8;
    const int r0 = row0 + rL0, r1 = r0 + 8;

    // phase 1: dual GEMM mu|lv, K=523
    float acc[4][4] = {};
    for (int tt = 0; tt < K1T; tt++) {
        const int kt = tt * 32;
        #pragma unroll
        for (int j = 0; j < 8; j++) {
            const int i = kt + ak4 + j;
            float v = 0.f;
            if (i < 523)
                v = (i < FRAME) ? __ldg(&x[(row0 + am4) * FRAME + i])
                                : __ldg(&h2[(row0 + am4) * HIDDEN + (i - FRAME)]);
            As[am4][ak4 + j] = tf32r(v);
        }
        {
            const int kg = kt + bk4;
            const bool kok = kg < 523;
            #pragma unroll
            for (int j = 0; j < 16; j++) {
                const int nl = bn4 + j;
                float v = 0.f;
                if (kok)
                    v = (nl < 32) ? __ldg(&wmu[kg * 32 + nl])
                                  : __ldg(&wlv[kg * 32 + (nl - 32)]);
                Bs[bk4][bn4 + j] = tf32r(v);
            }
        }
        __syncthreads();
        #pragma unroll
        for (int ks = 0; ks < 4; ks++) {
            const int kk = ks << 3;
            uint32_t a0 = __float_as_uint(As[rL0][kk + tg    ]);
            uint32_t a1 = __float_as_uint(As[rL1][kk + tg    ]);
            uint32_t a2 = __float_as_uint(As[rL0][kk + tg + 4]);
            uint32_t a3 = __float_as_uint(As[rL1][kk + tg + 4]);
            #pragma unroll
            for (int t = 0; t < 4; t++) {
                const int col = wn32 + (t << 3) + gid;
                uint32_t b0 = __float_as_uint(Bs[kk + tg    ][col]);
                uint32_t b1 = __float_as_uint(Bs[kk + tg + 4][col]);
                asm volatile(
                    "mma.sync.aligned.m16n8k8.row.col.f32.tf32.tf32.f32 "
                    "{%0,%1,%2,%3}, {%4,%5,%6,%7}, {%8,%9}, {%0,%1,%2,%3};\n"
                    : "+f"(acc[t][0]), "+f"(acc[t][1]),
                      "+f"(acc[t][2]), "+f"(acc[t][3])
                    : "r"(a0), "r"(a1), "r"(a2), "r"(a3), "r"(b0), "r"(b1));
            }
        }
        __syncthreads();
    }

    float muv[4][4];
    #pragma unroll
    for (int t = 0; t < 4; t++) {
        #pragma unroll
        for (int q = 0; q < 4; q++) {
            const int r  = (q < 2) ? r0 : r1;
            const int rL = (q < 2) ? rL0 : rL1;
            const int colL = wn32 + (t << 3) + (tg << 1) + (q & 1);
            if (colL < 32) {
                const float m_ = acc[t][q] + __ldg(&bmu[colL]);
                mu_out[r * 32 + colL] = m_;
                muv[t][q] = m_;
            } else {
                const int cl = colL - 32;
                const float l_ = acc[t][q] + __ldg(&blv[cl]);
                lv_out[r * 32 + cl] = l_;
                lvs[rL][cl] = l_;
            }
        }
    }
    __syncthreads();

    // phase 2: z = mu + eps*exp(0.5*lv)
    if (wid < 2) {
        #pragma unroll
        for (int t = 0; t < 4; t++) {
            #pragma unroll
            for (int q = 0; q < 4; q++) {
                const int r  = (q < 2) ? r0 : r1;
                const int rL = (q < 2) ? rL0 : rL1;
                const int colL = (t << 3) + (tg << 1) + (q & 1);
                const float zv = fmaf(__ldg(&epsv[r * 32 + colL]),
                                      expf(0.5f * lvs[rL][colL]), muv[t][q]);
                zs[rL][colL] = zv;
                zout[r * 32 + colL] = zv;
            }
        }
    }
    __syncthreads();

    // phase 3: gate0 GEMM, K=299, N=64
    float ac2[4][4] = {};
    for (int tt = 0; tt < K2T; tt++) {
        const int kt = tt * 32;
        #pragma unroll
        for (int j = 0; j < 8; j++) {
            const int i = kt + ak4 + j;
            float v = 0.f;
            if (i < 32)          v = zs[am4][i];
            else if (i < IN0)    v = __ldg(&cc[(row0 + am4) * FRAME + (i - 32)]);
            As[am4][ak4 + j] = tf32r(v);
        }
        {
            const int kg = kt + bk4;
            const bool kok = kg < IN0;
            #pragma unroll
            for (int j = 0; j < 16; j++) {
                const int nl = bn4 + j;
                Bs[bk4][bn4 + j] = tf32r(kok ? __ldg(&gw0[kg * 64 + nl]) : 0.f);
            }
        }
        __syncthreads();
        #pragma unroll
        for (int ks = 0; ks < 4; ks++) {
            const int kk = ks << 3;
            uint32_t a0 = __float_as_uint(As[rL0][kk + tg    ]);
            uint32_t a1 = __float_as_uint(As[rL1][kk + tg    ]);
            uint32_t a2 = __float_as_uint(As[rL0][kk + tg + 4]);
            uint32_t a3 = __float_as_uint(As[rL1][kk + tg + 4]);
            #pragma unroll
            for (int t = 0; t < 4; t++) {
                const int col = wn32 + (t << 3) + gid;
                uint32_t b0 = __float_as_uint(Bs[kk + tg    ][col]);
                uint32_t b1 = __float_as_uint(Bs[kk + tg + 4][col]);
                asm volatile(
                    "mma.sync.aligned.m16n8k8.row.col.f32.tf32.tf32.f32 "
                    "{%0,%1,%2,%3}, {%4,%5,%6,%7}, {%8,%9}, {%0,%1,%2,%3};\n"
                    : "+f"(ac2[t][0]), "+f"(ac2[t][1]),
                      "+f"(ac2[t][2]), "+f"(ac2[t][3])
                    : "r"(a0), "r"(a1), "r"(a2), "r"(a3), "r"(b0), "r"(b1));
            }
        }
        __syncthreads();
    }
    #pragma unroll
    for (int t = 0; t < 4; t++) {
        #pragma unroll
        for (int q = 0; q < 4; q++) {
            const int rL = (q < 2) ? rL0 : rL1;
            const int colL = wn32 + (t << 3) + (tg << 1) + (q & 1);
            g1s[rL][colL] = elu1(ac2[t][q] + __ldg(&gb0[colL]));
        }
    }
    __syncthreads();

    // phase 4: gate1 (64x64), w1 in smem
    for (int i = tid; i < 64 * 64; i += 128)
        w1s[i >> 6][i & 63] = __ldg(&gw1[i]);
    __syncthreads();
    {
        const int row = tid >> 2;
        const int cs  = tid & 3;
        float a16[16];
        #pragma unroll
        for (int j = 0; j < 16; j++) a16[j] = __ldg(&gb1[cs + (j << 2)]);
        #pragma unroll
        for (int k = 0; k < 64; k++) {
            const float gv = g1s[row][k];
            #pragma unroll
            for (int j = 0; j < 16; j++)
                a16[j] = fmaf(gv, w1s[k][cs + (j << 2)], a16[j]);
        }
        #pragma unroll
        for (int j = 0; j < 16; j++)
            g2s[row][cs + (j << 2)] = elu1(a16[j]);
    }
    __syncthreads();

    // phase 5: gate2 + softmax
    if (tid < 32) {
        float lg[EXPERTS];
        #pragma unroll
        for (int e = 0; e < EXPERTS; e++) lg[e] = __ldg(&gb2[e]);
        #pragma unroll
        for (int k = 0; k < 64; k++) {
            const float gv = g2s[tid][k];
            #pragma unroll
            for (int e = 0; e < EXPERTS; e++)
                lg[e] = fmaf(gv, __ldg(&gw2[k * EXPERTS + e]), lg[e]);
        }
        float mx = lg[0];
        #pragma unroll
        for (int e = 1; e < EXPERTS; e++) mx = fmaxf(mx, lg[e]);
        float s = 0.f;
        #pragma unroll
        for (int e = 0; e < EXPERTS; e++) { lg[e] = expf(lg[e] - mx); s += lg[e]; }
        const float inv = 1.f / s;
        #pragma unroll
        for (int e = 0; e < EXPERTS; e++)
            coeff[(row0 + tid) * EXPERTS + e] = lg[e] * inv;
    }
}

// ---------------- launch ----------------
extern "C" void kernel_launch(void* const* d_in, const int* in_sizes, int n_in,
                              void* d_out, int out_size)
{
    const float* x       = (const float*)d_in[0];
    const float* c       = (const float*)d_in[1];
    const float* eps     = (const float*)d_in[2];
    const float* enc_w1  = (const float*)d_in[3];
    const float* enc_b1  = (const float*)d_in[4];
    const float* enc_w2  = (const float*)d_in[5];
    const float* enc_b2  = (const float*)d_in[6];
    const float* enc_wmu = (const float*)d_in[7];
    const float* enc_bmu = (const float*)d_in[8];
    const float* enc_wlv = (const float*)d_in[9];
    const float* enc_blv = (const float*)d_in[10];
    const float* gw0     = (const float*)d_in[11];
    const float* gb0     = (const float*)d_in[12];
    const float* gw1     = (const float*)d_in[13];
    const float* gb1     = (const float*)d_in[14];
    const float* gw2     = (const float*)d_in[15];
    const float* gb2     = (const float*)d_in[16];
    const float* w0      = (const float*)d_in[17];
    const float* b0      = (const float*)d_in[18];
    const float* w1      = (const float*)d_in[19];
    const float* b1      = (const float*)d_in[20];
    const float* w2      = (const float*)d_in[21];
    const float* b2      = (const float*)d_in[22];
    float* out = (float*)d_out;

    float *h1, *h2, *z, *coef, *d1, *d2;
    cudaGetSymbolAddress((void**)&h1,   g_h1);
    cudaGetSymbolAddress((void**)&h2,   g_h2);
    cudaGetSymbolAddress((void**)&z,    g_zbuf);
    cudaGetSymbolAddress((void**)&coef, g_coef);
    cudaGetSymbolAddress((void**)&d1,   g_d1);
    cudaGetSymbolAddress((void**)&d2,   g_d2);

    const dim3 blk(256);
    const dim3 gridH(HIDDEN / 64, BATCH / 64);              // (4, 64)
    const dim3 gridO((OUTD + 63) / 64, BATCH / 64);         // (5, 64)

    // encoder layer 1: h1 = elu([x, c] @ enc_w1 + b1)   K=534
    mma_gemm<HIDDEN, FRAME, 2*FRAME, 1, 1><<<gridH, blk>>>(
        x, FRAME, c, FRAME, nullptr, enc_w1, enc_b1, h1, HIDDEN);
    // encoder layer 2: h2 = elu([x, h1] @ enc_w2 + b2)  K=523
    mma_gemm<HIDDEN, FRAME, FRAME+HIDDEN, 1, 1><<<gridH, blk>>>(
        x, FRAME, h1, HIDDEN, nullptr, enc_w2, enc_b2, h2, HIDDEN);
    // mid: mu/lv + z + gate0 + gate1 + gate2 + softmax
    mid_kernel<<<BATCH / 32, dim3(128)>>>(
        x, h2, enc_wmu, enc_bmu, enc_wlv, enc_blv, eps, c,
        gw0, gb0, gw1, gb1, gw2, gb2,
        out + OFF_MU, out + OFF_LV, z, coef);
    // MoE decoder layer 0: Ktot = 6*299 = 1794
    mma_gemm<HIDDEN, LATENT, IN0, EXPERTS, 1><<<gridH, blk>>>(
        z, LATENT, c, FRAME, coef, w0, b0, d1, HIDDEN);
    // MoE decoder layer 1: Ktot = 6*288 = 1728
    mma_gemm<HIDDEN, LATENT, IN1, EXPERTS, 1><<<gridH, blk>>>(
        z, LATENT, d1, HIDDEN, coef, w1, b1, d2, HIDDEN);
    // MoE decoder layer 2 (no act): N=267, Ktot=1728
    mma_gemm<OUTD, LATENT, IN1, EXPERTS, 0><<<gridO, blk>>>(
        z, LATENT, d2, HIDDEN, coef, w2, b2, out, OUTD);
}

// round 8
// speedup vs baseline: 2.5301x; 1.3650x over previous
#include <cuda_runtime.h>
#include <cstdint>

// ---------------- problem constants ----------------
#define BATCH   4096
#define FRAME   267
#define LATENT  32
#define HIDDEN  256
#define GATE_H  64
#define EXPERTS 6
#define IN0     (LATENT + FRAME)    // 299
#define IN1     (LATENT + HIDDEN)   // 288
#define OUTD    FRAME               // 267

#define OFF_MU  (BATCH * OUTD)
#define OFF_LV  (OFF_MU + BATCH * LATENT)

// ---------------- scratch (allocation-free) ----------------
__device__ float g_h1[BATCH * HIDDEN];
__device__ float g_h2[BATCH * HIDDEN];
__device__ float g_coef[BATCH * EXPERTS];
// packed decoder inputs (16B-aligned rows)
__device__ __align__(16) float g_q0[BATCH * 320];   // [z | c | 0pad]
__device__ __align__(16) float g_q1[BATCH * 288];   // [z | d1]
__device__ __align__(16) float g_q2[BATCH * 288];   // [z | d2]

__device__ __forceinline__ float elu1(float x) { return x > 0.f ? x : expm1f(x); }

__device__ __forceinline__ float tf32r(float x) {
    float y;
    asm("cvt.rna.tf32.f32 %0, %1;" : "=f"(y) : "f"(x));
    return y;
}

// ============================================================
// Encoder GEMM — R7-proven kernel, E=1 path only (verbatim).
// Tile 64x64x32, 256 threads, 8 warps (4m x 2n), warp tile m16n32.
// ============================================================
#define BK 32

template<int N_, int K0_, int DIN_, int ACT_>
__global__ __launch_bounds__(256) void enc_gemm(
    const float* __restrict__ A0, int lda0,
    const float* __restrict__ A1, int lda1,
    const float* __restrict__ W, const float* __restrict__ bias,
    float* __restrict__ C, int ldc)
{
    constexpr int Ktot = DIN_;
    __shared__ float As[64][36];
    __shared__ float Bs[32][72];

    const int tid  = threadIdx.x;
    const int lane = tid & 31;
    const int wid  = tid >> 5;
    const int wm16 = (wid >> 1) << 4;
    const int wn32 = (wid & 1) << 5;
    const int gid  = lane >> 2;
    const int tg   = lane & 3;

    const int bm_ = blockIdx.y * 64;
    const int bn_ = blockIdx.x * 64;

    const int amL = tid >> 3;
    const int akq = (tid & 7) << 2;
    const int bkL = tid >> 4;
    const int bnb = (tid & 15) << 2;

    float avv[2][4], bvv[2][4];

    auto ldgA = [&](int kt, float a[2][4]) {
        #pragma unroll
        for (int half = 0; half < 2; half++) {
            const int m = bm_ + amL + half * 32;
            #pragma unroll
            for (int j = 0; j < 4; j++) {
                const int ig = kt + akq + j;
                float val = 0.f;
                if ((Ktot % BK == 0) || ig < Ktot)
                    val = (ig < K0_) ? __ldg(&A0[m * lda0 + ig])
                                     : __ldg(&A1[m * lda1 + (ig - K0_)]);
                a[half][j] = val;
            }
        }
    };
    auto ldgB = [&](int kt, float b[2][4]) {
        #pragma unroll
        for (int half = 0; half < 2; half++) {
            const int kg = kt + bkL + half * 16;
            const bool kok = (Ktot % BK == 0) || (kg < Ktot);
            #pragma unroll
            for (int j = 0; j < 4; j++) {
                const int n = bn_ + bnb + j;
                float val = 0.f;
                if (kok && ((N_ % 64) == 0 || n < N_))
                    val = __ldg(&W[(size_t)kg * N_ + n]);
                b[half][j] = val;
            }
        }
    };
    auto sts = [&](float a[2][4], float b[2][4]) {
        #pragma unroll
        for (int half = 0; half < 2; half++) {
            const int mL = amL + half * 32;
            #pragma unroll
            for (int j = 0; j < 4; j++)
                As[mL][akq + j] = tf32r(a[half][j]);
        }
        #pragma unroll
        for (int half = 0; half < 2; half++) {
            const int kL = bkL + half * 16;
            #pragma unroll
            for (int j = 0; j < 4; j++)
                Bs[kL][bnb + j] = tf32r(b[half][j]);
        }
    };

    float acc[4][4] = {};

    ldgA(0, avv); ldgB(0, bvv);
    for (int kt = 0; kt < Ktot; kt += BK) {
        sts(avv, bvv);
        __syncthreads();

        float avn[2][4], bvn[2][4];
        const bool more = (kt + BK < Ktot);
        if (more) { ldgA(kt + BK, avn); ldgB(kt + BK, bvn); }

        #pragma unroll
        for (int ks = 0; ks < 4; ks++) {
            const int kk = ks << 3;
            uint32_t a0 = __float_as_uint(As[wm16 + gid    ][kk + tg    ]);
            uint32_t a1 = __float_as_uint(As[wm16 + gid + 8][kk + tg    ]);
            uint32_t a2 = __float_as_uint(As[wm16 + gid    ][kk + tg + 4]);
            uint32_t a3 = __float_as_uint(As[wm16 + gid + 8][kk + tg + 4]);
            #pragma unroll
            for (int t = 0; t < 4; t++) {
                const int col = wn32 + (t << 3) + gid;
                uint32_t b0 = __float_as_uint(Bs[kk + tg    ][col]);
                uint32_t b1 = __float_as_uint(Bs[kk + tg + 4][col]);
                asm volatile(
                    "mma.sync.aligned.m16n8k8.row.col.f32.tf32.tf32.f32 "
                    "{%0,%1,%2,%3}, {%4,%5,%6,%7}, {%8,%9}, {%0,%1,%2,%3};\n"
                    : "+f"(acc[t][0]), "+f"(acc[t][1]),
                      "+f"(acc[t][2]), "+f"(acc[t][3])
                    : "r"(a0), "r"(a1), "r"(a2), "r"(a3), "r"(b0), "r"(b1));
            }
        }
        __syncthreads();

        if (more) {
            #pragma unroll
            for (int h = 0; h < 2; h++)
                #pragma unroll
                for (int j = 0; j < 4; j++) {
                    avv[h][j] = avn[h][j];
                    bvv[h][j] = bvn[h][j];
                }
        }
    }

    const int r0 = bm_ + wm16 + gid;
    const int r1 = r0 + 8;
    #pragma unroll
    for (int t = 0; t < 4; t++) {
        #pragma unroll
        for (int q = 0; q < 4; q++) {
            const int r  = (q < 2) ? r0 : r1;
            const int colL = wn32 + (t << 3) + (tg << 1) + (q & 1);
            const int cG = bn_ + colL;
            if ((N_ % 64) == 0 || cG < N_) {
                float v = acc[t][q] + __ldg(&bias[cG]);
                if (ACT_ == 1) v = elu1(v);
                C[r * ldc + cG] = v;
            }
        }
    }
}

// ============================================================
// Decoder GEMM — packed aligned A, vectorized loads/stores.
//   C[m,n] = act( sum over flat K of cf[m,e]*A[m, e-local i]*W_e[i,n] + cf@b )
// A: packed [BATCH][LDA_] rows = [z | layer | 0pad], DINP_ = padded K per
// expert (mult of 32). B pad rows (kl >= DINR_) are zeroed, so A pad values
// contribute nothing. Tile 64x64x32, 256 thr, warp tile m16n32 (R2 layout).
// ============================================================
template<int N_, int DINR_, int DINP_, int LDA_, int ACT_>
__global__ __launch_bounds__(256) void dec_gemm(
    const float* __restrict__ A,
    const float* __restrict__ coeff,
    const float* __restrict__ W, const float* __restrict__ bias,
    float* __restrict__ C, int ldc)
{
    constexpr int E_  = EXPERTS;
    constexpr int TPE = DINP_ / 32;
    constexpr int NT  = E_ * TPE;
    __shared__ __align__(16) float As[64][36];
    __shared__ __align__(16) float Bs[32][72];

    const int tid  = threadIdx.x;
    const int lane = tid & 31;
    const int wid  = tid >> 5;
    const int wm16 = (wid >> 1) << 4;
    const int wn32 = (wid & 1) << 5;
    const int gid  = lane >> 2;
    const int tg   = lane & 3;

    const int bm_ = blockIdx.y * 64;
    const int bn_ = blockIdx.x * 64;

    const int amL = tid >> 3;            // 0..31 (+32 second half)
    const int akq = (tid & 7) << 2;      // 0..28
    const int bkL = tid >> 4;            // 0..15 (+16 second half)
    const int bnb = (tid & 15) << 2;     // 0..60

    const float* Ar0  = A + (bm_ + amL) * LDA_;
    const float* Ar1  = Ar0 + 32 * LDA_;
    const float* cf0p = coeff + (bm_ + amL) * E_;
    const float* cf1p = cf0p + 32 * E_;

    float avv[2][4], bvv[2][4];

    auto ldgA = [&](int t, float a[2][4]) {
        const int e  = t / TPE;                      // compile-time TPE: mul-shift
        const int i0 = (t - e * TPE) * 32 + akq;     // always in [0, DINP_-4]
        const float c0 = __ldg(&cf0p[e]);
        const float c1 = __ldg(&cf1p[e]);
        const float4 v0 = __ldg(reinterpret_cast<const float4*>(Ar0 + i0));
        const float4 v1 = __ldg(reinterpret_cast<const float4*>(Ar1 + i0));
        a[0][0] = v0.x * c0; a[0][1] = v0.y * c0; a[0][2] = v0.z * c0; a[0][3] = v0.w * c0;
        a[1][0] = v1.x * c1; a[1][1] = v1.y * c1; a[1][2] = v1.z * c1; a[1][3] = v1.w * c1;
    };
    auto ldgB = [&](int t, float b[2][4]) {
        const int e  = t / TPE;
        const int k0 = (t - e * TPE) * 32;
        const float* We = W + (size_t)e * DINR_ * N_;
        #pragma unroll
        for (int half = 0; half < 2; half++) {
            const int kl = k0 + bkL + half * 16;
            const bool kok = (DINR_ == DINP_) || (kl < DINR_);
            if ((N_ % 64) == 0) {
                float4 v = make_float4(0.f, 0.f, 0.f, 0.f);
                if (kok)
                    v = __ldg(reinterpret_cast<const float4*>(We + (size_t)kl * N_ + bn_ + bnb));
                b[half][0] = v.x; b[half][1] = v.y; b[half][2] = v.z; b[half][3] = v.w;
            } else {
                #pragma unroll
                for (int j = 0; j < 4; j++) {
                    const int n = bn_ + bnb + j;
                    float v = 0.f;
                    if (kok && n < N_) v = __ldg(&We[(size_t)kl * N_ + n]);
                    b[half][j] = v;
                }
            }
        }
    };
    auto sts = [&](float a[2][4], float b[2][4]) {
        #pragma unroll
        for (int half = 0; half < 2; half++) {
            const float4 t4 = make_float4(tf32r(a[half][0]), tf32r(a[half][1]),
                                          tf32r(a[half][2]), tf32r(a[half][3]));
            *reinterpret_cast<float4*>(&As[amL + half * 32][akq]) = t4;
        }
        #pragma unroll
        for (int half = 0; half < 2; half++) {
            const float4 t4 = make_float4(tf32r(b[half][0]), tf32r(b[half][1]),
                                          tf32r(b[half][2]), tf32r(b[half][3]));
            *reinterpret_cast<float4*>(&Bs[bkL + half * 16][bnb]) = t4;
        }
    };

    float acc[4][4] = {};

    ldgA(0, avv); ldgB(0, bvv);
    for (int t = 0; t < NT; t++) {
        sts(avv, bvv);
        __syncthreads();

        float avn[2][4], bvn[2][4];
        const bool more = (t + 1 < NT);
        if (more) { ldgA(t + 1, avn); ldgB(t + 1, bvn); }

        #pragma unroll
        for (int ks = 0; ks < 4; ks++) {
            const int kk = ks << 3;
            uint32_t a0 = __float_as_uint(As[wm16 + gid    ][kk + tg    ]);
            uint32_t a1 = __float_as_uint(As[wm16 + gid + 8][kk + tg    ]);
            uint32_t a2 = __float_as_uint(As[wm16 + gid    ][kk + tg + 4]);
            uint32_t a3 = __float_as_uint(As[wm16 + gid + 8][kk + tg + 4]);
            #pragma unroll
            for (int t4i = 0; t4i < 4; t4i++) {
                const int col = wn32 + (t4i << 3) + gid;
                uint32_t b0 = __float_as_uint(Bs[kk + tg    ][col]);
                uint32_t b1 = __float_as_uint(Bs[kk + tg + 4][col]);
                asm volatile(
                    "mma.sync.aligned.m16n8k8.row.col.f32.tf32.tf32.f32 "
                    "{%0,%1,%2,%3}, {%4,%5,%6,%7}, {%8,%9}, {%0,%1,%2,%3};\n"
                    : "+f"(acc[t4i][0]), "+f"(acc[t4i][1]),
                      "+f"(acc[t4i][2]), "+f"(acc[t4i][3])
                    : "r"(a0), "r"(a1), "r"(a2), "r"(a3), "r"(b0), "r"(b1));
            }
        }
        __syncthreads();

        if (more) {
            #pragma unroll
            for (int h = 0; h < 2; h++)
                #pragma unroll
                for (int j = 0; j < 4; j++) {
                    avv[h][j] = avn[h][j];
                    bvv[h][j] = bvn[h][j];
                }
        }
    }

    // ---- epilogue (blended bias) ----
    const int r0 = bm_ + wm16 + gid;
    const int r1 = r0 + 8;
    float cf0[E_], cf1[E_];
    #pragma unroll
    for (int e = 0; e < E_; e++) {
        cf0[e] = coeff[r0 * E_ + e];
        cf1[e] = coeff[r1 * E_ + e];
    }

    #pragma unroll
    for (int t = 0; t < 4; t++) {
        #pragma unroll
        for (int q = 0; q < 4; q++) {
            const int r  = (q < 2) ? r0 : r1;
            const int colL = wn32 + (t << 3) + (tg << 1) + (q & 1);
            const int cG = bn_ + colL;
            if ((N_ % 64) == 0 || cG < N_) {
                const float* cf = (q < 2) ? cf0 : cf1;
                float bb = 0.f;
                #pragma unroll
                for (int e = 0; e < E_; e++)
                    bb = fmaf(cf[e], __ldg(&bias[e * N_ + cG]), bb);
                float v = acc[t][q] + bb;
                if (ACT_ == 1) v = elu1(v);
                C[r * ldc + cG] = v;
            }
        }
    }
}

// ---------------- pack kernel: c -> q0 cols [32, 320) ----------------
__global__ void pack_c(const float* __restrict__ c, float* __restrict__ q0)
{
    int idx = blockIdx.x * blockDim.x + threadIdx.x;
    if (idx >= BATCH * 288) return;
    const int r = idx / 288;
    const int col = 32 + idx % 288;     // 32..319
    q0[r * 320 + col] = (col < IN0) ? c[r * FRAME + (col - 32)] : 0.f;
}

// ============================================================
// mid kernel (R7 verbatim, except z is written into q0/q1/q2):
// mu/lv dual GEMM (K=523) -> z -> gate0 -> gate1 -> gate2 -> softmax.
// 128 threads, 32 rows per block, grid = 128.
// ============================================================
#define K1T 17   // ceil(523/32)
#define K2T 10   // ceil(299/32)

__global__ __launch_bounds__(128) void mid_kernel(
    const float* __restrict__ x,   const float* __restrict__ h2,
    const float* __restrict__ wmu, const float* __restrict__ bmu,
    const float* __restrict__ wlv, const float* __restrict__ blv,
    const float* __restrict__ epsv, const float* __restrict__ cc,
    const float* __restrict__ gw0, const float* __restrict__ gb0,
    const float* __restrict__ gw1, const float* __restrict__ gb1,
    const float* __restrict__ gw2, const float* __restrict__ gb2,
    float* __restrict__ mu_out, float* __restrict__ lv_out,
    float* __restrict__ q0, float* __restrict__ q1, float* __restrict__ q2,
    float* __restrict__ coeff)
{
    __shared__ float SMEM[9728];
    float (*As)[36]  = (float(*)[36]) (SMEM);
    float (*Bs)[72]  = (float(*)[72]) (SMEM + 1152);
    float (*zs)[33]  = (float(*)[33]) (SMEM + 3456);
    float (*lvs)[33] = (float(*)[33]) (SMEM + 4512);
    float (*g1s)[65] = (float(*)[65]) (SMEM + 5568);
    float (*g2s)[65] = (float(*)[65]) (SMEM + 7648);
    float (*w1s)[68] = (float(*)[68]) (SMEM);          // phase-4 overlay

    const int tid  = threadIdx.x;
    const int lane = tid & 31;
    const int wid  = tid >> 5;
    const int wm16 = (wid & 1) << 4;
    const int wn32 = (wid >> 1) << 5;
    const int gid  = lane >> 2;
    const int tg   = lane & 3;
    const int row0 = blockIdx.x * 32;

    const int am4 = tid >> 2;
    const int ak4 = (tid & 3) << 3;
    const int bk4 = tid >> 2;
    const int bn4 = (tid & 3) << 4;

    const int rL0 = wm16 + gid, rL1 = rL0 + 8;
    const int r0 = row0 + rL0, r1 = r0 + 8;

    // phase 1: dual GEMM mu|lv, K=523
    float acc[4][4] = {};
    for (int tt = 0; tt < K1T; tt++) {
        const int kt = tt * 32;
        #pragma unroll
        for (int j = 0; j < 8; j++) {
            const int i = kt + ak4 + j;
            float v = 0.f;
            if (i < 523)
                v = (i < FRAME) ? __ldg(&x[(row0 + am4) * FRAME + i])
                                : __ldg(&h2[(row0 + am4) * HIDDEN + (i - FRAME)]);
            As[am4][ak4 + j] = tf32r(v);
        }
        {
            const int kg = kt + bk4;
            const bool kok = kg < 523;
            #pragma unroll
            for (int j = 0; j < 16; j++) {
                const int nl = bn4 + j;
                float v = 0.f;
                if (kok)
                    v = (nl < 32) ? __ldg(&wmu[kg * 32 + nl])
                                  : __ldg(&wlv[kg * 32 + (nl - 32)]);
                Bs[bk4][bn4 + j] = tf32r(v);
            }
        }
        __syncthreads();
        #pragma unroll
        for (int ks = 0; ks < 4; ks++) {
            const int kk = ks << 3;
            uint32_t a0 = __float_as_uint(As[rL0][kk + tg    ]);
            uint32_t a1 = __float_as_uint(As[rL1][kk + tg    ]);
            uint32_t a2 = __float_as_uint(As[rL0][kk + tg + 4]);
            uint32_t a3 = __float_as_uint(As[rL1][kk + tg + 4]);
            #pragma unroll
            for (int t = 0; t < 4; t++) {
                const int col = wn32 + (t << 3) + gid;
                uint32_t b0 = __float_as_uint(Bs[kk + tg    ][col]);
                uint32_t b1 = __float_as_uint(Bs[kk + tg + 4][col]);
                asm volatile(
                    "mma.sync.aligned.m16n8k8.row.col.f32.tf32.tf32.f32 "
                    "{%0,%1,%2,%3}, {%4,%5,%6,%7}, {%8,%9}, {%0,%1,%2,%3};\n"
                    : "+f"(acc[t][0]), "+f"(acc[t][1]),
                      "+f"(acc[t][2]), "+f"(acc[t][3])
                    : "r"(a0), "r"(a1), "r"(a2), "r"(a3), "r"(b0), "r"(b1));
            }
        }
        __syncthreads();
    }

    float muv[4][4];
    #pragma unroll
    for (int t = 0; t < 4; t++) {
        #pragma unroll
        for (int q = 0; q < 4; q++) {
            const int r  = (q < 2) ? r0 : r1;
            const int rL = (q < 2) ? rL0 : rL1;
            const int colL = wn32 + (t << 3) + (tg << 1) + (q & 1);
            if (colL < 32) {
                const float m_ = acc[t][q] + __ldg(&bmu[colL]);
                mu_out[r * 32 + colL] = m_;
                muv[t][q] = m_;
            } else {
                const int cl = colL - 32;
                const float l_ = acc[t][q] + __ldg(&blv[cl]);
                lv_out[r * 32 + cl] = l_;
                lvs[rL][cl] = l_;
            }
        }
    }
    __syncthreads();

    // phase 2: z = mu + eps*exp(0.5*lv)  ->  q0/q1/q2 cols [0,32)
    if (wid < 2) {
        #pragma unroll
        for (int t = 0; t < 4; t++) {
            #pragma unroll
            for (int q = 0; q < 4; q++) {
                const int r  = (q < 2) ? r0 : r1;
                const int rL = (q < 2) ? rL0 : rL1;
                const int colL = (t << 3) + (tg << 1) + (q & 1);
                const float zv = fmaf(__ldg(&epsv[r * 32 + colL]),
                                      expf(0.5f * lvs[rL][colL]), muv[t][q]);
                zs[rL][colL] = zv;
                q0[r * 320 + colL] = zv;
                q1[r * 288 + colL] = zv;
                q2[r * 288 + colL] = zv;
            }
        }
    }
    __syncthreads();

    // phase 3: gate0 GEMM, K=299, N=64
    float ac2[4][4] = {};
    for (int tt = 0; tt < K2T; tt++) {
        const int kt = tt * 32;
        #pragma unroll
        for (int j = 0; j < 8; j++) {
            const int i = kt + ak4 + j;
            float v = 0.f;
            if (i < 32)          v = zs[am4][i];
            else if (i < IN0)    v = __ldg(&cc[(row0 + am4) * FRAME + (i - 32)]);
            As[am4][ak4 + j] = tf32r(v);
        }
        {
            const int kg = kt + bk4;
            const bool kok = kg < IN0;
            #pragma unroll
            for (int j = 0; j < 16; j++) {
                const int nl = bn4 + j;
                Bs[bk4][bn4 + j] = tf32r(kok ? __ldg(&gw0[kg * 64 + nl]) : 0.f);
            }
        }
        __syncthreads();
        #pragma unroll
        for (int ks = 0; ks < 4; ks++) {
            const int kk = ks << 3;
            uint32_t a0 = __float_as_uint(As[rL0][kk + tg    ]);
            uint32_t a1 = __float_as_uint(As[rL1][kk + tg    ]);
            uint32_t a2 = __float_as_uint(As[rL0][kk + tg + 4]);
            uint32_t a3 = __float_as_uint(As[rL1][kk + tg + 4]);
            #pragma unroll
            for (int t = 0; t < 4; t++) {
                const int col = wn32 + (t << 3) + gid;
                uint32_t b0 = __float_as_uint(Bs[kk + tg    ][col]);
                uint32_t b1 = __float_as_uint(Bs[kk + tg + 4][col]);
                asm volatile(
                    "mma.sync.aligned.m16n8k8.row.col.f32.tf32.tf32.f32 "
                    "{%0,%1,%2,%3}, {%4,%5,%6,%7}, {%8,%9}, {%0,%1,%2,%3};\n"
                    : "+f"(ac2[t][0]), "+f"(ac2[t][1]),
                      "+f"(ac2[t][2]), "+f"(ac2[t][3])
                    : "r"(a0), "r"(a1), "r"(a2), "r"(a3), "r"(b0), "r"(b1));
            }
        }
        __syncthreads();
    }
    #pragma unroll
    for (int t = 0; t < 4; t++) {
        #pragma unroll
        for (int q = 0; q < 4; q++) {
            const int rL = (q < 2) ? rL0 : rL1;
            const int colL = wn32 + (t << 3) + (tg << 1) + (q & 1);
            g1s[rL][colL] = elu1(ac2[t][q] + __ldg(&gb0[colL]));
        }
    }
    __syncthreads();

    // phase 4: gate1 (64x64), w1 in smem
    for (int i = tid; i < 64 * 64; i += 128)
        w1s[i >> 6][i & 63] = __ldg(&gw1[i]);
    __syncthreads();
    {
        const int row = tid >> 2;
        const int cs  = tid & 3;
        float a16[16];
        #pragma unroll
        for (int j = 0; j < 16; j++) a16[j] = __ldg(&gb1[cs + (j << 2)]);
        #pragma unroll
        for (int k = 0; k < 64; k++) {
            const float gv = g1s[row][k];
            #pragma unroll
            for (int j = 0; j < 16; j++)
                a16[j] = fmaf(gv, w1s[k][cs + (j << 2)], a16[j]);
        }
        #pragma unroll
        for (int j = 0; j < 16; j++)
            g2s[row][cs + (j << 2)] = elu1(a16[j]);
    }
    __syncthreads();

    // phase 5: gate2 + softmax
    if (tid < 32) {
        float lg[EXPERTS];
        #pragma unroll
        for (int e = 0; e < EXPERTS; e++) lg[e] = __ldg(&gb2[e]);
        #pragma unroll
        for (int k = 0; k < 64; k++) {
            const float gv = g2s[tid][k];
            #pragma unroll
            for (int e = 0; e < EXPERTS; e++)
                lg[e] = fmaf(gv, __ldg(&gw2[k * EXPERTS + e]), lg[e]);
        }
        float mx = lg[0];
        #pragma unroll
        for (int e = 1; e < EXPERTS; e++) mx = fmaxf(mx, lg[e]);
        float s = 0.f;
        #pragma unroll
        for (int e = 0; e < EXPERTS; e++) { lg[e] = expf(lg[e] - mx); s += lg[e]; }
        const float inv = 1.f / s;
        #pragma unroll
        for (int e = 0; e < EXPERTS; e++)
            coeff[(row0 + tid) * EXPERTS + e] = lg[e] * inv;
    }
}

// ---------------- launch ----------------
extern "C" void kernel_launch(void* const* d_in, const int* in_sizes, int n_in,
                              void* d_out, int out_size)
{
    const float* x       = (const float*)d_in[0];
    const float* c       = (const float*)d_in[1];
    const float* eps     = (const float*)d_in[2];
    const float* enc_w1  = (const float*)d_in[3];
    const float* enc_b1  = (const float*)d_in[4];
    const float* enc_w2  = (const float*)d_in[5];
    const float* enc_b2  = (const float*)d_in[6];
    const float* enc_wmu = (const float*)d_in[7];
    const float* enc_bmu = (const float*)d_in[8];
    const float* enc_wlv = (const float*)d_in[9];
    const float* enc_blv = (const float*)d_in[10];
    const float* gw0     = (const float*)d_in[11];
    const float* gb0     = (const float*)d_in[12];
    const float* gw1     = (const float*)d_in[13];
    const float* gb1     = (const float*)d_in[14];
    const float* gw2     = (const float*)d_in[15];
    const float* gb2     = (const float*)d_in[16];
    const float* w0      = (const float*)d_in[17];
    const float* b0      = (const float*)d_in[18];
    const float* w1      = (const float*)d_in[19];
    const float* b1      = (const float*)d_in[20];
    const float* w2      = (const float*)d_in[21];
    const float* b2      = (const float*)d_in[22];
    float* out = (float*)d_out;

    float *h1, *h2, *coef, *q0, *q1, *q2;
    cudaGetSymbolAddress((void**)&h1,   g_h1);
    cudaGetSymbolAddress((void**)&h2,   g_h2);
    cudaGetSymbolAddress((void**)&coef, g_coef);
    cudaGetSymbolAddress((void**)&q0,   g_q0);
    cudaGetSymbolAddress((void**)&q1,   g_q1);
    cudaGetSymbolAddress((void**)&q2,   g_q2);

    const dim3 blk(256);
    const dim3 gridH(HIDDEN / 64, BATCH / 64);              // (4, 64)
    const dim3 gridO((OUTD + 63) / 64, BATCH / 64);         // (5, 64)

    // pack c into q0 cols [32,320) (independent of everything else)
    pack_c<<<(BATCH * 288 + 255) / 256, 256>>>(c, q0);
    // encoder layer 1: h1 = elu([x, c] @ enc_w1 + b1)   K=534
    enc_gemm<HIDDEN, FRAME, 2*FRAME, 1><<<gridH, blk>>>(
        x, FRAME, c, FRAME, enc_w1, enc_b1, h1, HIDDEN);
    // encoder layer 2: h2 = elu([x, h1] @ enc_w2 + b2)  K=523
    enc_gemm<HIDDEN, FRAME, FRAME+HIDDEN, 1><<<gridH, blk>>>(
        x, FRAME, h1, HIDDEN, enc_w2, enc_b2, h2, HIDDEN);
    // mid: mu/lv + z (into q0/q1/q2) + gate0 + gate1 + gate2 + softmax
    mid_kernel<<<BATCH / 32, dim3(128)>>>(
        x, h2, enc_wmu, enc_bmu, enc_wlv, enc_blv, eps, c,
        gw0, gb0, gw1, gb1, gw2, gb2,
        out + OFF_MU, out + OFF_LV, q0, q1, q2, coef);
    // MoE decoder layer 0: DIN 299 (pad 320) -> d1 into q1 cols [32,288)
    dec_gemm<HIDDEN, IN0, 320, 320, 1><<<gridH, blk>>>(
        q0, coef, w0, b0, q1 + 32, IN1);
    // MoE decoder layer 1: DIN 288 exact -> d2 into q2 cols [32,288)
    dec_gemm<HIDDEN, IN1, 288, 288, 1><<<gridH, blk>>>(
        q1, coef, w1, b1, q2 + 32, IN1);
    // MoE decoder layer 2 (no act): N=267 -> output
    dec_gemm<OUTD, IN1, 288, 288, 0><<<gridO, blk>>>(
        q2, coef, w2, b2, out, OUTD);
}

// round 9
// speedup vs baseline: 2.7677x; 1.0939x over previous
#include <cuda_runtime.h>
#include <cstdint>

// ---------------- problem constants ----------------
#define BATCH   4096
#define FRAME   267
#define LATENT  32
#define HIDDEN  256
#define GATE_H  64
#define EXPERTS 6
#define IN0     (LATENT + FRAME)    // 299
#define IN1     (LATENT + HIDDEN)   // 288
#define OUTD    FRAME               // 267

#define OFF_MU  (BATCH * OUTD)
#define OFF_LV  (OFF_MU + BATCH * LATENT)

// ---------------- scratch (allocation-free) ----------------
__device__ float g_h1[BATCH * HIDDEN];
__device__ float g_h2[BATCH * HIDDEN];
__device__ float g_g1[BATCH * GATE_H];
__device__ float g_coef[BATCH * EXPERTS];
// packed decoder inputs (16B-aligned rows)
__device__ __align__(16) float g_q0[BATCH * 320];   // [z | c | 0pad]
__device__ __align__(16) float g_q1[BATCH * 288];   // [z | d1]
__device__ __align__(16) float g_q2[BATCH * 288];   // [z | d2]

__device__ __forceinline__ float elu1(float x) { return x > 0.f ? x : expm1f(x); }

__device__ __forceinline__ float tf32r(float x) {
    float y;
    asm("cvt.rna.tf32.f32 %0, %1;" : "=f"(y) : "f"(x));
    return y;
}

#define BK 32

// ============================================================
// Encoder/gate GEMM — R8-proven kernel (verbatim).
// Tile 64x64x32, 256 threads, 8 warps (4m x 2n), warp tile m16n32.
// ============================================================
template<int N_, int K0_, int DIN_, int ACT_>
__global__ __launch_bounds__(256) void enc_gemm(
    const float* __restrict__ A0, int lda0,
    const float* __restrict__ A1, int lda1,
    const float* __restrict__ W, const float* __restrict__ bias,
    float* __restrict__ C, int ldc)
{
    constexpr int Ktot = DIN_;
    __shared__ float As[64][36];
    __shared__ float Bs[32][72];

    const int tid  = threadIdx.x;
    const int lane = tid & 31;
    const int wid  = tid >> 5;
    const int wm16 = (wid >> 1) << 4;
    const int wn32 = (wid & 1) << 5;
    const int gid  = lane >> 2;
    const int tg   = lane & 3;

    const int bm_ = blockIdx.y * 64;
    const int bn_ = blockIdx.x * 64;

    const int amL = tid >> 3;
    const int akq = (tid & 7) << 2;
    const int bkL = tid >> 4;
    const int bnb = (tid & 15) << 2;

    float avv[2][4], bvv[2][4];

    auto ldgA = [&](int kt, float a[2][4]) {
        #pragma unroll
        for (int half = 0; half < 2; half++) {
            const int m = bm_ + amL + half * 32;
            #pragma unroll
            for (int j = 0; j < 4; j++) {
                const int ig = kt + akq + j;
                float val = 0.f;
                if ((Ktot % BK == 0) || ig < Ktot)
                    val = (ig < K0_) ? __ldg(&A0[m * lda0 + ig])
                                     : __ldg(&A1[m * lda1 + (ig - K0_)]);
                a[half][j] = val;
            }
        }
    };
    auto ldgB = [&](int kt, float b[2][4]) {
        #pragma unroll
        for (int half = 0; half < 2; half++) {
            const int kg = kt + bkL + half * 16;
            const bool kok = (Ktot % BK == 0) || (kg < Ktot);
            #pragma unroll
            for (int j = 0; j < 4; j++) {
                const int n = bn_ + bnb + j;
                float val = 0.f;
                if (kok && ((N_ % 64) == 0 || n < N_))
                    val = __ldg(&W[(size_t)kg * N_ + n]);
                b[half][j] = val;
            }
        }
    };
    auto sts = [&](float a[2][4], float b[2][4]) {
        #pragma unroll
        for (int half = 0; half < 2; half++) {
            const int mL = amL + half * 32;
            #pragma unroll
            for (int j = 0; j < 4; j++)
                As[mL][akq + j] = tf32r(a[half][j]);
        }
        #pragma unroll
        for (int half = 0; half < 2; half++) {
            const int kL = bkL + half * 16;
            #pragma unroll
            for (int j = 0; j < 4; j++)
                Bs[kL][bnb + j] = tf32r(b[half][j]);
        }
    };

    float acc[4][4] = {};

    ldgA(0, avv); ldgB(0, bvv);
    for (int kt = 0; kt < Ktot; kt += BK) {
        sts(avv, bvv);
        __syncthreads();

        float avn[2][4], bvn[2][4];
        const bool more = (kt + BK < Ktot);
        if (more) { ldgA(kt + BK, avn); ldgB(kt + BK, bvn); }

        #pragma unroll
        for (int ks = 0; ks < 4; ks++) {
            const int kk = ks << 3;
            uint32_t a0 = __float_as_uint(As[wm16 + gid    ][kk + tg    ]);
            uint32_t a1 = __float_as_uint(As[wm16 + gid + 8][kk + tg    ]);
            uint32_t a2 = __float_as_uint(As[wm16 + gid    ][kk + tg + 4]);
            uint32_t a3 = __float_as_uint(As[wm16 + gid + 8][kk + tg + 4]);
            #pragma unroll
            for (int t = 0; t < 4; t++) {
                const int col = wn32 + (t << 3) + gid;
                uint32_t b0 = __float_as_uint(Bs[kk + tg    ][col]);
                uint32_t b1 = __float_as_uint(Bs[kk + tg + 4][col]);
                asm volatile(
                    "mma.sync.aligned.m16n8k8.row.col.f32.tf32.tf32.f32 "
                    "{%0,%1,%2,%3}, {%4,%5,%6,%7}, {%8,%9}, {%0,%1,%2,%3};\n"
                    : "+f"(acc[t][0]), "+f"(acc[t][1]),
                      "+f"(acc[t][2]), "+f"(acc[t][3])
                    : "r"(a0), "r"(a1), "r"(a2), "r"(a3), "r"(b0), "r"(b1));
            }
        }
        __syncthreads();

        if (more) {
            #pragma unroll
            for (int h = 0; h < 2; h++)
                #pragma unroll
                for (int j = 0; j < 4; j++) {
                    avv[h][j] = avn[h][j];
                    bvv[h][j] = bvn[h][j];
                }
        }
    }

    const int r0 = bm_ + wm16 + gid;
    const int r1 = r0 + 8;
    #pragma unroll
    for (int t = 0; t < 4; t++) {
        #pragma unroll
        for (int q = 0; q < 4; q++) {
            const int r  = (q < 2) ? r0 : r1;
            const int colL = wn32 + (t << 3) + (tg << 1) + (q & 1);
            const int cG = bn_ + colL;
            if ((N_ % 64) == 0 || cG < N_) {
                float v = acc[t][q] + __ldg(&bias[cG]);
                if (ACT_ == 1) v = elu1(v);
                C[r * ldc + cG] = v;
            }
        }
    }
}

// ============================================================
// dual_gemm: mu|lv (N=64: [wmu | wlv]) + fused reparameterization z.
// Same skeleton as enc_gemm (64x64x32, 256 thr); epilogue writes mu/lv
// to output and smem, then z = mu + eps*exp(0.5*lv) into q0/q1/q2.
// grid (1, 64).
// ============================================================
__global__ __launch_bounds__(256) void dual_gemm(
    const float* __restrict__ x,   const float* __restrict__ h2,
    const float* __restrict__ wmu, const float* __restrict__ bmu,
    const float* __restrict__ wlv, const float* __restrict__ blv,
    const float* __restrict__ epsv,
    float* __restrict__ mu_out, float* __restrict__ lv_out,
    float* __restrict__ q0, float* __restrict__ q1, float* __restrict__ q2)
{
    constexpr int Ktot = FRAME + HIDDEN;   // 523
    __shared__ float As[64][36];
    __shared__ float Bs[32][72];

    const int tid  = threadIdx.x;
    const int lane = tid & 31;
    const int wid  = tid >> 5;
    const int wm16 = (wid >> 1) << 4;
    const int wn32 = (wid & 1) << 5;
    const int gid  = lane >> 2;
    const int tg   = lane & 3;

    const int bm_ = blockIdx.y * 64;

    const int amL = tid >> 3;
    const int akq = (tid & 7) << 2;
    const int bkL = tid >> 4;
    const int bnb = (tid & 15) << 2;

    float avv[2][4], bvv[2][4];

    auto ldgA = [&](int kt, float a[2][4]) {
        #pragma unroll
        for (int half = 0; half < 2; half++) {
            const int m = bm_ + amL + half * 32;
            #pragma unroll
            for (int j = 0; j < 4; j++) {
                const int ig = kt + akq + j;
                float val = 0.f;
                if (ig < Ktot)
                    val = (ig < FRAME) ? __ldg(&x[m * FRAME + ig])
                                       : __ldg(&h2[m * HIDDEN + (ig - FRAME)]);
                a[half][j] = val;
            }
        }
    };
    auto ldgB = [&](int kt, float b[2][4]) {
        #pragma unroll
        for (int half = 0; half < 2; half++) {
            const int kg = kt + bkL + half * 16;
            const bool kok = kg < Ktot;
            #pragma unroll
            for (int j = 0; j < 4; j++) {
                const int nl = bnb + j;
                float val = 0.f;
                if (kok)
                    val = (nl < 32) ? __ldg(&wmu[kg * 32 + nl])
                                    : __ldg(&wlv[kg * 32 + (nl - 32)]);
                b[half][j] = val;
            }
        }
    };
    auto sts = [&](float a[2][4], float b[2][4]) {
        #pragma unroll
        for (int half = 0; half < 2; half++) {
            const int mL = amL + half * 32;
            #pragma unroll
            for (int j = 0; j < 4; j++)
                As[mL][akq + j] = tf32r(a[half][j]);
        }
        #pragma unroll
        for (int half = 0; half < 2; half++) {
            const int kL = bkL + half * 16;
            #pragma unroll
            for (int j = 0; j < 4; j++)
                Bs[kL][bnb + j] = tf32r(b[half][j]);
        }
    };

    float acc[4][4] = {};

    ldgA(0, avv); ldgB(0, bvv);
    for (int kt = 0; kt < Ktot; kt += BK) {
        sts(avv, bvv);
        __syncthreads();

        float avn[2][4], bvn[2][4];
        const bool more = (kt + BK < Ktot);
        if (more) { ldgA(kt + BK, avn); ldgB(kt + BK, bvn); }

        #pragma unroll
        for (int ks = 0; ks < 4; ks++) {
            const int kk = ks << 3;
            uint32_t a0 = __float_as_uint(As[wm16 + gid    ][kk + tg    ]);
            uint32_t a1 = __float_as_uint(As[wm16 + gid + 8][kk + tg    ]);
            uint32_t a2 = __float_as_uint(As[wm16 + gid    ][kk + tg + 4]);
            uint32_t a3 = __float_as_uint(As[wm16 + gid + 8][kk + tg + 4]);
            #pragma unroll
            for (int t = 0; t < 4; t++) {
                const int col = wn32 + (t << 3) + gid;
                uint32_t b0 = __float_as_uint(Bs[kk + tg    ][col]);
                uint32_t b1 = __float_as_uint(Bs[kk + tg + 4][col]);
                asm volatile(
                    "mma.sync.aligned.m16n8k8.row.col.f32.tf32.tf32.f32 "
                    "{%0,%1,%2,%3}, {%4,%5,%6,%7}, {%8,%9}, {%0,%1,%2,%3};\n"
                    : "+f"(acc[t][0]), "+f"(acc[t][1]),
                      "+f"(acc[t][2]), "+f"(acc[t][3])
                    : "r"(a0), "r"(a1), "r"(a2), "r"(a3), "r"(b0), "r"(b1));
            }
        }
        __syncthreads();

        if (more) {
            #pragma unroll
            for (int h = 0; h < 2; h++)
                #pragma unroll
                for (int j = 0; j < 4; j++) {
                    avv[h][j] = avn[h][j];
                    bvv[h][j] = bvn[h][j];
                }
        }
    }

    // epilogue: mu/lv out + smem exchange (reuse As/Bs as [64][33])
    float* muS = &As[0][0];
    float* lvS = &Bs[0][0];

    const int r0 = bm_ + wm16 + gid;
    const int r1 = r0 + 8;
    #pragma unroll
    for (int t = 0; t < 4; t++) {
        #pragma unroll
        for (int q = 0; q < 4; q++) {
            const int r  = (q < 2) ? r0 : r1;
            const int rL = r - bm_;
            const int colL = wn32 + (t << 3) + (tg << 1) + (q & 1);
            if (colL < 32) {
                const float m_ = acc[t][q] + __ldg(&bmu[colL]);
                mu_out[r * 32 + colL] = m_;
                muS[rL * 33 + colL] = m_;
            } else {
                const int cl = colL - 32;
                const float l_ = acc[t][q] + __ldg(&blv[cl]);
                lv_out[r * 32 + cl] = l_;
                lvS[rL * 33 + cl] = l_;
            }
        }
    }
    __syncthreads();

    // fused z
    for (int e = tid; e < 64 * 32; e += 256) {
        const int rL = e >> 5, cl = e & 31;
        const int r = bm_ + rL;
        const float zv = fmaf(__ldg(&epsv[r * 32 + cl]),
                              expf(0.5f * lvS[rL * 33 + cl]), muS[rL * 33 + cl]);
        q0[r * 320 + cl] = zv;
        q1[r * 288 + cl] = zv;
        q2[r * 288 + cl] = zv;
    }
}

// ============================================================
// Decoder GEMM — R8-proven (verbatim): packed aligned A, vector loads.
// ============================================================
template<int N_, int DINR_, int DINP_, int LDA_, int ACT_>
__global__ __launch_bounds__(256) void dec_gemm(
    const float* __restrict__ A,
    const float* __restrict__ coeff,
    const float* __restrict__ W, const float* __restrict__ bias,
    float* __restrict__ C, int ldc)
{
    constexpr int E_  = EXPERTS;
    constexpr int TPE = DINP_ / 32;
    constexpr int NT  = E_ * TPE;
    __shared__ __align__(16) float As[64][36];
    __shared__ __align__(16) float Bs[32][72];

    const int tid  = threadIdx.x;
    const int lane = tid & 31;
    const int wid  = tid >> 5;
    const int wm16 = (wid >> 1) << 4;
    const int wn32 = (wid & 1) << 5;
    const int gid  = lane >> 2;
    const int tg   = lane & 3;

    const int bm_ = blockIdx.y * 64;
    const int bn_ = blockIdx.x * 64;

    const int amL = tid >> 3;
    const int akq = (tid & 7) << 2;
    const int bkL = tid >> 4;
    const int bnb = (tid & 15) << 2;

    const float* Ar0  = A + (bm_ + amL) * LDA_;
    const float* Ar1  = Ar0 + 32 * LDA_;
    const float* cf0p = coeff + (bm_ + amL) * E_;
    const float* cf1p = cf0p + 32 * E_;

    float avv[2][4], bvv[2][4];

    auto ldgA = [&](int t, float a[2][4]) {
        const int e  = t / TPE;
        const int i0 = (t - e * TPE) * 32 + akq;
        const float c0 = __ldg(&cf0p[e]);
        const float c1 = __ldg(&cf1p[e]);
        const float4 v0 = __ldg(reinterpret_cast<const float4*>(Ar0 + i0));
        const float4 v1 = __ldg(reinterpret_cast<const float4*>(Ar1 + i0));
        a[0][0] = v0.x * c0; a[0][1] = v0.y * c0; a[0][2] = v0.z * c0; a[0][3] = v0.w * c0;
        a[1][0] = v1.x * c1; a[1][1] = v1.y * c1; a[1][2] = v1.z * c1; a[1][3] = v1.w * c1;
    };
    auto ldgB = [&](int t, float b[2][4]) {
        const int e  = t / TPE;
        const int k0 = (t - e * TPE) * 32;
        const float* We = W + (size_t)e * DINR_ * N_;
        #pragma unroll
        for (int half = 0; half < 2; half++) {
            const int kl = k0 + bkL + half * 16;
            const bool kok = (DINR_ == DINP_) || (kl < DINR_);
            if ((N_ % 64) == 0) {
                float4 v = make_float4(0.f, 0.f, 0.f, 0.f);
                if (kok)
                    v = __ldg(reinterpret_cast<const float4*>(We + (size_t)kl * N_ + bn_ + bnb));
                b[half][0] = v.x; b[half][1] = v.y; b[half][2] = v.z; b[half][3] = v.w;
            } else {
                #pragma unroll
                for (int j = 0; j < 4; j++) {
                    const int n = bn_ + bnb + j;
                    float v = 0.f;
                    if (kok && n < N_) v = __ldg(&We[(size_t)kl * N_ + n]);
                    b[half][j] = v;
                }
            }
        }
    };
    auto sts = [&](float a[2][4], float b[2][4]) {
        #pragma unroll
        for (int half = 0; half < 2; half++) {
            const float4 t4 = make_float4(tf32r(a[half][0]), tf32r(a[half][1]),
                                          tf32r(a[half][2]), tf32r(a[half][3]));
            *reinterpret_cast<float4*>(&As[amL + half * 32][akq]) = t4;
        }
        #pragma unroll
        for (int half = 0; half < 2; half++) {
            const float4 t4 = make_float4(tf32r(b[half][0]), tf32r(b[half][1]),
                                          tf32r(b[half][2]), tf32r(b[half][3]));
            *reinterpret_cast<float4*>(&Bs[bkL + half * 16][bnb]) = t4;
        }
    };

    float acc[4][4] = {};

    ldgA(0, avv); ldgB(0, bvv);
    for (int t = 0; t < NT; t++) {
        sts(avv, bvv);
        __syncthreads();

        float avn[2][4], bvn[2][4];
        const bool more = (t + 1 < NT);
        if (more) { ldgA(t + 1, avn); ldgB(t + 1, bvn); }

        #pragma unroll
        for (int ks = 0; ks < 4; ks++) {
            const int kk = ks << 3;
            uint32_t a0 = __float_as_uint(As[wm16 + gid    ][kk + tg    ]);
            uint32_t a1 = __float_as_uint(As[wm16 + gid + 8][kk + tg    ]);
            uint32_t a2 = __float_as_uint(As[wm16 + gid    ][kk + tg + 4]);
            uint32_t a3 = __float_as_uint(As[wm16 + gid + 8][kk + tg + 4]);
            #pragma unroll
            for (int t4i = 0; t4i < 4; t4i++) {
                const int col = wn32 + (t4i << 3) + gid;
                uint32_t b0 = __float_as_uint(Bs[kk + tg    ][col]);
                uint32_t b1 = __float_as_uint(Bs[kk + tg + 4][col]);
                asm volatile(
                    "mma.sync.aligned.m16n8k8.row.col.f32.tf32.tf32.f32 "
                    "{%0,%1,%2,%3}, {%4,%5,%6,%7}, {%8,%9}, {%0,%1,%2,%3};\n"
                    : "+f"(acc[t4i][0]), "+f"(acc[t4i][1]),
                      "+f"(acc[t4i][2]), "+f"(acc[t4i][3])
                    : "r"(a0), "r"(a1), "r"(a2), "r"(a3), "r"(b0), "r"(b1));
            }
        }
        __syncthreads();

        if (more) {
            #pragma unroll
            for (int h = 0; h < 2; h++)
                #pragma unroll
                for (int j = 0; j < 4; j++) {
                    avv[h][j] = avn[h][j];
                    bvv[h][j] = bvn[h][j];
                }
        }
    }

    const int r0 = bm_ + wm16 + gid;
    const int r1 = r0 + 8;
    float cf0[E_], cf1[E_];
    #pragma unroll
    for (int e = 0; e < E_; e++) {
        cf0[e] = coeff[r0 * E_ + e];
        cf1[e] = coeff[r1 * E_ + e];
    }

    #pragma unroll
    for (int t = 0; t < 4; t++) {
        #pragma unroll
        for (int q = 0; q < 4; q++) {
            const int r  = (q < 2) ? r0 : r1;
            const int colL = wn32 + (t << 3) + (tg << 1) + (q & 1);
            const int cG = bn_ + colL;
            if ((N_ % 64) == 0 || cG < N_) {
                const float* cf = (q < 2) ? cf0 : cf1;
                float bb = 0.f;
                #pragma unroll
                for (int e = 0; e < E_; e++)
                    bb = fmaf(cf[e], __ldg(&bias[e * N_ + cG]), bb);
                float v = acc[t][q] + bb;
                if (ACT_ == 1) v = elu1(v);
                C[r * ldc + cG] = v;
            }
        }
    }
}

// ---------------- pack kernel: c -> q0 cols [32, 320) ----------------
__global__ void pack_c(const float* __restrict__ c, float* __restrict__ q0)
{
    int idx = blockIdx.x * blockDim.x + threadIdx.x;
    if (idx >= BATCH * 288) return;
    const int r = idx / 288;
    const int col = 32 + idx % 288;     // 32..319
    q0[r * 320 + col] = (col < IN0) ? c[r * FRAME + (col - 32)] : 0.f;
}

// ---------------- fused gate layer1 + layer2 + softmax (R2-proven) ---
__global__ __launch_bounds__(256) void gate12_softmax(
    const float* __restrict__ g1, const float* __restrict__ w1,
    const float* __restrict__ b1, const float* __restrict__ w2,
    const float* __restrict__ b2, float* __restrict__ coeff)
{
    __shared__ float w1s[64][65];
    __shared__ float w2s[64][8];
    __shared__ float b1s[64];
    __shared__ float g1s[32][64];
    __shared__ float g2s[32][65];

    const int tid = threadIdx.x;
    const int row0 = blockIdx.x * 32;

    for (int i = tid; i < 64 * 64; i += 256) w1s[i >> 6][i & 63] = w1[i];
    for (int i = tid; i < 64 * EXPERTS; i += 256) w2s[i / EXPERTS][i % EXPERTS] = w2[i];
    if (tid < 64) b1s[tid] = b1[tid];
    for (int i = tid; i < 32 * 64; i += 256)
        g1s[i >> 6][i & 63] = g1[(row0 + (i >> 6)) * GATE_H + (i & 63)];
    __syncthreads();

    const int ri = tid >> 3;
    const int c0 = (tid & 7) << 3;
    float acc[8];
    #pragma unroll
    for (int c = 0; c < 8; c++) acc[c] = b1s[c0 + c];
    #pragma unroll
    for (int k = 0; k < 64; k++) {
        const float gv = g1s[ri][k];
        #pragma unroll
        for (int c = 0; c < 8; c++) acc[c] = fmaf(gv, w1s[k][c0 + c], acc[c]);
    }
    #pragma unroll
    for (int c = 0; c < 8; c++) g2s[ri][c0 + c] = elu1(acc[c]);
    __syncthreads();

    if (tid < 32) {
        float lg[EXPERTS];
        #pragma unroll
        for (int e = 0; e < EXPERTS; e++) lg[e] = b2[e];
        #pragma unroll
        for (int k = 0; k < 64; k++) {
            const float gv = g2s[tid][k];
            #pragma unroll
            for (int e = 0; e < EXPERTS; e++) lg[e] = fmaf(gv, w2s[k][e], lg[e]);
        }
        float mx = lg[0];
        #pragma unroll
        for (int e = 1; e < EXPERTS; e++) mx = fmaxf(mx, lg[e]);
        float s = 0.f;
        #pragma unroll
        for (int e = 0; e < EXPERTS; e++) { lg[e] = expf(lg[e] - mx); s += lg[e]; }
        const float inv = 1.f / s;
        #pragma unroll
        for (int e = 0; e < EXPERTS; e++)
            coeff[(row0 + tid) * EXPERTS + e] = lg[e] * inv;
    }
}

// ---------------- launch ----------------
extern "C" void kernel_launch(void* const* d_in, const int* in_sizes, int n_in,
                              void* d_out, int out_size)
{
    const float* x       = (const float*)d_in[0];
    const float* c       = (const float*)d_in[1];
    const float* eps     = (const float*)d_in[2];
    const float* enc_w1  = (const float*)d_in[3];
    const float* enc_b1  = (const float*)d_in[4];
    const float* enc_w2  = (const float*)d_in[5];
    const float* enc_b2  = (const float*)d_in[6];
    const float* enc_wmu = (const float*)d_in[7];
    const float* enc_bmu = (const float*)d_in[8];
    const float* enc_wlv = (const float*)d_in[9];
    const float* enc_blv = (const float*)d_in[10];
    const float* gw0     = (const float*)d_in[11];
    const float* gb0     = (const float*)d_in[12];
    const float* gw1     = (const float*)d_in[13];
    const float* gb1     = (const float*)d_in[14];
    const float* gw2     = (const float*)d_in[15];
    const float* gb2     = (const float*)d_in[16];
    const float* w0      = (const float*)d_in[17];
    const float* b0      = (const float*)d_in[18];
    const float* w1      = (const float*)d_in[19];
    const float* b1      = (const float*)d_in[20];
    const float* w2      = (const float*)d_in[21];
    const float* b2      = (const float*)d_in[22];
    float* out = (float*)d_out;

    float *h1, *h2, *g1, *coef, *q0, *q1, *q2;
    cudaGetSymbolAddress((void**)&h1,   g_h1);
    cudaGetSymbolAddress((void**)&h2,   g_h2);
    cudaGetSymbolAddress((void**)&g1,   g_g1);
    cudaGetSymbolAddress((void**)&coef, g_coef);
    cudaGetSymbolAddress((void**)&q0,   g_q0);
    cudaGetSymbolAddress((void**)&q1,   g_q1);
    cudaGetSymbolAddress((void**)&q2,   g_q2);

    const dim3 blk(256);
    const dim3 gridH(HIDDEN / 64, BATCH / 64);              // (4, 64)
    const dim3 grid1(1, BATCH / 64);                        // (1, 64)
    const dim3 gridO((OUTD + 63) / 64, BATCH / 64);         // (5, 64)

    // pack c into q0 cols [32,320)
    pack_c<<<(BATCH * 288 + 255) / 256, 256>>>(c, q0);
    // encoder layer 1: h1 = elu([x, c] @ enc_w1 + b1)   K=534
    enc_gemm<HIDDEN, FRAME, 2*FRAME, 1><<<gridH, blk>>>(
        x, FRAME, c, FRAME, enc_w1, enc_b1, h1, HIDDEN);
    // encoder layer 2: h2 = elu([x, h1] @ enc_w2 + b2)  K=523
    enc_gemm<HIDDEN, FRAME, FRAME+HIDDEN, 1><<<gridH, blk>>>(
        x, FRAME, h1, HIDDEN, enc_w2, enc_b2, h2, HIDDEN);
    // mu|lv + fused z into q0/q1/q2
    dual_gemm<<<grid1, blk>>>(
        x, h2, enc_wmu, enc_bmu, enc_wlv, enc_blv, eps,
        out + OFF_MU, out + OFF_LV, q0, q1, q2);
    // gate0: g1 = elu(q0row @ gw0 + gb0), K=299 (q0 row is [z|c|pad])
    enc_gemm<GATE_H, 320, IN0, 1><<<grid1, blk>>>(
        q0, 320, q0, 320, gw0, gb0, g1, GATE_H);
    // gate1 + gate2 + softmax -> coeff
    gate12_softmax<<<BATCH / 32, blk>>>(g1, gw1, gb1, gw2, gb2, coef);
    // MoE decoder layer 0: DIN 299 (pad 320) -> d1 into q1 cols [32,288)
    dec_gemm<HIDDEN, IN0, 320, 320, 1><<<gridH, blk>>>(
        q0, coef, w0, b0, q1 + 32, IN1);
    // MoE decoder layer 1: DIN 288 exact -> d2 into q2 cols [32,288)
    dec_gemm<HIDDEN, IN1, 288, 288, 1><<<gridH, blk>>>(
        q1, coef, w1, b1, q2 + 32, IN1);
    // MoE decoder layer 2 (no act): N=267 -> output
    dec_gemm<OUTD, IN1, 288, 288, 0><<<gridO, blk>>>(
        q2, coef, w2, b2, out, OUTD);
}

// round 10
// speedup vs baseline: 2.7703x; 1.0009x over previous
#include <cuda_runtime.h>
#include <cstdint>

// ---------------- problem constants ----------------
#define BATCH   4096
#define FRAME   267
#define LATENT  32
#define HIDDEN  256
#define GATE_H  64
#define EXPERTS 6
#define IN0     (LATENT + FRAME)    // 299
#define IN1     (LATENT + HIDDEN)   // 288
#define OUTD    FRAME               // 267

#define OFF_MU  (BATCH * OUTD)
#define OFF_LV  (OFF_MU + BATCH * LATENT)

// ---------------- scratch (allocation-free) ----------------
__device__ float g_h1[BATCH * HIDDEN];
__device__ float g_h2[BATCH * HIDDEN];
__device__ float g_g1[BATCH * GATE_H];
__device__ float g_coef[BATCH * EXPERTS];
// packed decoder inputs (16B-aligned rows)
__device__ __align__(16) float g_q0[BATCH * 320];   // [z | c | 0pad]
__device__ __align__(16) float g_q1[BATCH * 288];   // [z | d1]
__device__ __align__(16) float g_q2[BATCH * 288];   // [z | d2]

__device__ __forceinline__ float elu1(float x) { return x > 0.f ? x : expm1f(x); }

__device__ __forceinline__ float tf32r(float x) {
    float y;
    asm("cvt.rna.tf32.f32 %0, %1;" : "=f"(y) : "f"(x));
    return y;
}

#define BK 32

// ============================================================
// Encoder/gate GEMM — R8-proven indexing, double-buffered smem
// (single __syncthreads per k-tile).
// Tile 64x64x32, 256 threads, 8 warps (4m x 2n), warp tile m16n32.
// ============================================================
template<int N_, int K0_, int DIN_, int ACT_>
__global__ __launch_bounds__(256) void enc_gemm(
    const float* __restrict__ A0, int lda0,
    const float* __restrict__ A1, int lda1,
    const float* __restrict__ W, const float* __restrict__ bias,
    float* __restrict__ C, int ldc)
{
    constexpr int Ktot = DIN_;
    constexpr int NT   = (Ktot + BK - 1) / BK;
    __shared__ float As[2][64][36];
    __shared__ float Bs[2][32][72];

    const int tid  = threadIdx.x;
    const int lane = tid & 31;
    const int wid  = tid >> 5;
    const int wm16 = (wid >> 1) << 4;
    const int wn32 = (wid & 1) << 5;
    const int gid  = lane >> 2;
    const int tg   = lane & 3;

    const int bm_ = blockIdx.y * 64;
    const int bn_ = blockIdx.x * 64;

    const int amL = tid >> 3;
    const int akq = (tid & 7) << 2;
    const int bkL = tid >> 4;
    const int bnb = (tid & 15) << 2;

    float avv[2][4], bvv[2][4];

    auto ldgA = [&](int t) {
        const int kt = t * BK;
        #pragma unroll
        for (int half = 0; half < 2; half++) {
            const int m = bm_ + amL + half * 32;
            #pragma unroll
            for (int j = 0; j < 4; j++) {
                const int ig = kt + akq + j;
                float val = 0.f;
                if ((Ktot % BK == 0) || ig < Ktot)
                    val = (ig < K0_) ? __ldg(&A0[m * lda0 + ig])
                                     : __ldg(&A1[m * lda1 + (ig - K0_)]);
                avv[half][j] = val;
            }
        }
    };
    auto ldgB = [&](int t) {
        const int kt = t * BK;
        #pragma unroll
        for (int half = 0; half < 2; half++) {
            const int kg = kt + bkL + half * 16;
            const bool kok = (Ktot % BK == 0) || (kg < Ktot);
            #pragma unroll
            for (int j = 0; j < 4; j++) {
                const int n = bn_ + bnb + j;
                float val = 0.f;
                if (kok && ((N_ % 64) == 0 || n < N_))
                    val = __ldg(&W[(size_t)kg * N_ + n]);
                bvv[half][j] = val;
            }
        }
    };
    auto sts = [&](int buf) {
        #pragma unroll
        for (int half = 0; half < 2; half++) {
            const int mL = amL + half * 32;
            #pragma unroll
            for (int j = 0; j < 4; j++)
                As[buf][mL][akq + j] = tf32r(avv[half][j]);
        }
        #pragma unroll
        for (int half = 0; half < 2; half++) {
            const int kL = bkL + half * 16;
            #pragma unroll
            for (int j = 0; j < 4; j++)
                Bs[buf][kL][bnb + j] = tf32r(bvv[half][j]);
        }
    };

    float acc[4][4] = {};

    ldgA(0); ldgB(0);
    sts(0);
    __syncthreads();

    for (int t = 0; t < NT; t++) {
        const int cur = t & 1;
        const bool more = (t + 1 < NT);
        if (more) { ldgA(t + 1); ldgB(t + 1); }

        #pragma unroll
        for (int ks = 0; ks < 4; ks++) {
            const int kk = ks << 3;
            uint32_t a0 = __float_as_uint(As[cur][wm16 + gid    ][kk + tg    ]);
            uint32_t a1 = __float_as_uint(As[cur][wm16 + gid + 8][kk + tg    ]);
            uint32_t a2 = __float_as_uint(As[cur][wm16 + gid    ][kk + tg + 4]);
            uint32_t a3 = __float_as_uint(As[cur][wm16 + gid + 8][kk + tg + 4]);
            #pragma unroll
            for (int t4 = 0; t4 < 4; t4++) {
                const int col = wn32 + (t4 << 3) + gid;
                uint32_t b0 = __float_as_uint(Bs[cur][kk + tg    ][col]);
                uint32_t b1 = __float_as_uint(Bs[cur][kk + tg + 4][col]);
                asm volatile(
                    "mma.sync.aligned.m16n8k8.row.col.f32.tf32.tf32.f32 "
                    "{%0,%1,%2,%3}, {%4,%5,%6,%7}, {%8,%9}, {%0,%1,%2,%3};\n"
                    : "+f"(acc[t4][0]), "+f"(acc[t4][1]),
                      "+f"(acc[t4][2]), "+f"(acc[t4][3])
                    : "r"(a0), "r"(a1), "r"(a2), "r"(a3), "r"(b0), "r"(b1));
            }
        }
        if (more) sts(1 - cur);
        __syncthreads();
    }

    const int r0 = bm_ + wm16 + gid;
    const int r1 = r0 + 8;
    #pragma unroll
    for (int t = 0; t < 4; t++) {
        #pragma unroll
        for (int q = 0; q < 4; q++) {
            const int r  = (q < 2) ? r0 : r1;
            const int colL = wn32 + (t << 3) + (tg << 1) + (q & 1);
            const int cG = bn_ + colL;
            if ((N_ % 64) == 0 || cG < N_) {
                float v = acc[t][q] + __ldg(&bias[cG]);
                if (ACT_ == 1) v = elu1(v);
                C[r * ldc + cG] = v;
            }
        }
    }
}

// ============================================================
// dual_gemm: mu|lv (N=64: [wmu | wlv]) + fused z. Double-buffered.
// grid (1, 64), 256 threads.
// ============================================================
__global__ __launch_bounds__(256) void dual_gemm(
    const float* __restrict__ x,   const float* __restrict__ h2,
    const float* __restrict__ wmu, const float* __restrict__ bmu,
    const float* __restrict__ wlv, const float* __restrict__ blv,
    const float* __restrict__ epsv,
    float* __restrict__ mu_out, float* __restrict__ lv_out,
    float* __restrict__ q0, float* __restrict__ q1, float* __restrict__ q2)
{
    constexpr int Ktot = FRAME + HIDDEN;   // 523
    constexpr int NT   = (Ktot + BK - 1) / BK;   // 17
    __shared__ float As[2][64][36];
    __shared__ float Bs[2][32][72];

    const int tid  = threadIdx.x;
    const int lane = tid & 31;
    const int wid  = tid >> 5;
    const int wm16 = (wid >> 1) << 4;
    const int wn32 = (wid & 1) << 5;
    const int gid  = lane >> 2;
    const int tg   = lane & 3;

    const int bm_ = blockIdx.y * 64;

    const int amL = tid >> 3;
    const int akq = (tid & 7) << 2;
    const int bkL = tid >> 4;
    const int bnb = (tid & 15) << 2;

    float avv[2][4], bvv[2][4];

    auto ldgA = [&](int t) {
        const int kt = t * BK;
        #pragma unroll
        for (int half = 0; half < 2; half++) {
            const int m = bm_ + amL + half * 32;
            #pragma unroll
            for (int j = 0; j < 4; j++) {
                const int ig = kt + akq + j;
                float val = 0.f;
                if (ig < Ktot)
                    val = (ig < FRAME) ? __ldg(&x[m * FRAME + ig])
                                       : __ldg(&h2[m * HIDDEN + (ig - FRAME)]);
                avv[half][j] = val;
            }
        }
    };
    auto ldgB = [&](int t) {
        const int kt = t * BK;
        #pragma unroll
        for (int half = 0; half < 2; half++) {
            const int kg = kt + bkL + half * 16;
            const bool kok = kg < Ktot;
            #pragma unroll
            for (int j = 0; j < 4; j++) {
                const int nl = bnb + j;
                float val = 0.f;
                if (kok)
                    val = (nl < 32) ? __ldg(&wmu[kg * 32 + nl])
                                    : __ldg(&wlv[kg * 32 + (nl - 32)]);
                bvv[half][j] = val;
            }
        }
    };
    auto sts = [&](int buf) {
        #pragma unroll
        for (int half = 0; half < 2; half++) {
            const int mL = amL + half * 32;
            #pragma unroll
            for (int j = 0; j < 4; j++)
                As[buf][mL][akq + j] = tf32r(avv[half][j]);
        }
        #pragma unroll
        for (int half = 0; half < 2; half++) {
            const int kL = bkL + half * 16;
            #pragma unroll
            for (int j = 0; j < 4; j++)
                Bs[buf][kL][bnb + j] = tf32r(bvv[half][j]);
        }
    };

    float acc[4][4] = {};

    ldgA(0); ldgB(0);
    sts(0);
    __syncthreads();

    for (int t = 0; t < NT; t++) {
        const int cur = t & 1;
        const bool more = (t + 1 < NT);
        if (more) { ldgA(t + 1); ldgB(t + 1); }

        #pragma unroll
        for (int ks = 0; ks < 4; ks++) {
            const int kk = ks << 3;
            uint32_t a0 = __float_as_uint(As[cur][wm16 + gid    ][kk + tg    ]);
            uint32_t a1 = __float_as_uint(As[cur][wm16 + gid + 8][kk + tg    ]);
            uint32_t a2 = __float_as_uint(As[cur][wm16 + gid    ][kk + tg + 4]);
            uint32_t a3 = __float_as_uint(As[cur][wm16 + gid + 8][kk + tg + 4]);
            #pragma unroll
            for (int t4 = 0; t4 < 4; t4++) {
                const int col = wn32 + (t4 << 3) + gid;
                uint32_t b0 = __float_as_uint(Bs[cur][kk + tg    ][col]);
                uint32_t b1 = __float_as_uint(Bs[cur][kk + tg + 4][col]);
                asm volatile(
                    "mma.sync.aligned.m16n8k8.row.col.f32.tf32.tf32.f32 "
                    "{%0,%1,%2,%3}, {%4,%5,%6,%7}, {%8,%9}, {%0,%1,%2,%3};\n"
                    : "+f"(acc[t4][0]), "+f"(acc[t4][1]),
                      "+f"(acc[t4][2]), "+f"(acc[t4][3])
                    : "r"(a0), "r"(a1), "r"(a2), "r"(a3), "r"(b0), "r"(b1));
            }
        }
        if (more) sts(1 - cur);
        __syncthreads();
    }

    // epilogue: mu/lv out + smem exchange (reuse As buf0 / Bs buf0 as [64][33])
    float* muS = &As[0][0][0];
    float* lvS = &Bs[0][0][0];

    const int r0 = bm_ + wm16 + gid;
    const int r1 = r0 + 8;
    #pragma unroll
    for (int t = 0; t < 4; t++) {
        #pragma unroll
        for (int q = 0; q < 4; q++) {
            const int r  = (q < 2) ? r0 : r1;
            const int rL = r - bm_;
            const int colL = wn32 + (t << 3) + (tg << 1) + (q & 1);
            if (colL < 32) {
                const float m_ = acc[t][q] + __ldg(&bmu[colL]);
                mu_out[r * 32 + colL] = m_;
                muS[rL * 33 + colL] = m_;
            } else {
                const int cl = colL - 32;
                const float l_ = acc[t][q] + __ldg(&blv[cl]);
                lv_out[r * 32 + cl] = l_;
                lvS[rL * 33 + cl] = l_;
            }
        }
    }
    __syncthreads();

    for (int e = tid; e < 64 * 32; e += 256) {
        const int rL = e >> 5, cl = e & 31;
        const int r = bm_ + rL;
        const float zv = fmaf(__ldg(&epsv[r * 32 + cl]),
                              expf(0.5f * lvS[rL * 33 + cl]), muS[rL * 33 + cl]);
        q0[r * 320 + cl] = zv;
        q1[r * 288 + cl] = zv;
        q2[r * 288 + cl] = zv;
    }
}

// ============================================================
// Decoder GEMM — R8-proven indexing, double-buffered smem.
// ============================================================
template<int N_, int DINR_, int DINP_, int LDA_, int ACT_>
__global__ __launch_bounds__(256) void dec_gemm(
    const float* __restrict__ A,
    const float* __restrict__ coeff,
    const float* __restrict__ W, const float* __restrict__ bias,
    float* __restrict__ C, int ldc)
{
    constexpr int E_  = EXPERTS;
    constexpr int TPE = DINP_ / 32;
    constexpr int NT  = E_ * TPE;
    __shared__ __align__(16) float As[2][64][36];
    __shared__ __align__(16) float Bs[2][32][72];

    const int tid  = threadIdx.x;
    const int lane = tid & 31;
    const int wid  = tid >> 5;
    const int wm16 = (wid >> 1) << 4;
    const int wn32 = (wid & 1) << 5;
    const int gid  = lane >> 2;
    const int tg   = lane & 3;

    const int bm_ = blockIdx.y * 64;
    const int bn_ = blockIdx.x * 64;

    const int amL = tid >> 3;
    const int akq = (tid & 7) << 2;
    const int bkL = tid >> 4;
    const int bnb = (tid & 15) << 2;

    const float* Ar0  = A + (bm_ + amL) * LDA_;
    const float* Ar1  = Ar0 + 32 * LDA_;
    const float* cf0p = coeff + (bm_ + amL) * E_;
    const float* cf1p = cf0p + 32 * E_;

    float avv[2][4], bvv[2][4];

    auto ldgA = [&](int t) {
        const int e  = t / TPE;
        const int i0 = (t - e * TPE) * 32 + akq;
        const float c0 = __ldg(&cf0p[e]);
        const float c1 = __ldg(&cf1p[e]);
        const float4 v0 = __ldg(reinterpret_cast<const float4*>(Ar0 + i0));
        const float4 v1 = __ldg(reinterpret_cast<const float4*>(Ar1 + i0));
        avv[0][0] = v0.x * c0; avv[0][1] = v0.y * c0; avv[0][2] = v0.z * c0; avv[0][3] = v0.w * c0;
        avv[1][0] = v1.x * c1; avv[1][1] = v1.y * c1; avv[1][2] = v1.z * c1; avv[1][3] = v1.w * c1;
    };
    auto ldgB = [&](int t) {
        const int e  = t / TPE;
        const int k0 = (t - e * TPE) * 32;
        const float* We = W + (size_t)e * DINR_ * N_;
        #pragma unroll
        for (int half = 0; half < 2; half++) {
            const int kl = k0 + bkL + half * 16;
            const bool kok = (DINR_ == DINP_) || (kl < DINR_);
            if ((N_ % 64) == 0) {
                float4 v = make_float4(0.f, 0.f, 0.f, 0.f);
                if (kok)
                    v = __ldg(reinterpret_cast<const float4*>(We + (size_t)kl * N_ + bn_ + bnb));
                bvv[half][0] = v.x; bvv[half][1] = v.y; bvv[half][2] = v.z; bvv[half][3] = v.w;
            } else {
                #pragma unroll
                for (int j = 0; j < 4; j++) {
                    const int n = bn_ + bnb + j;
                    float v = 0.f;
                    if (kok && n < N_) v = __ldg(&We[(size_t)kl * N_ + n]);
                    bvv[half][j] = v;
                }
            }
        }
    };
    auto sts = [&](int buf) {
        #pragma unroll
        for (int half = 0; half < 2; half++) {
            const float4 t4 = make_float4(tf32r(avv[half][0]), tf32r(avv[half][1]),
                                          tf32r(avv[half][2]), tf32r(avv[half][3]));
            *reinterpret_cast<float4*>(&As[buf][amL + half * 32][akq]) = t4;
        }
        #pragma unroll
        for (int half = 0; half < 2; half++) {
            const float4 t4 = make_float4(tf32r(bvv[half][0]), tf32r(bvv[half][1]),
                                          tf32r(bvv[half][2]), tf32r(bvv[half][3]));
            *reinterpret_cast<float4*>(&Bs[buf][bkL + half * 16][bnb]) = t4;
        }
    };

    float acc[4][4] = {};

    ldgA(0); ldgB(0);
    sts(0);
    __syncthreads();

    for (int t = 0; t < NT; t++) {
        const int cur = t & 1;
        const bool more = (t + 1 < NT);
        if (more) { ldgA(t + 1); ldgB(t + 1); }

        #pragma unroll
        for (int ks = 0; ks < 4; ks++) {
            const int kk = ks << 3;
            uint32_t a0 = __float_as_uint(As[cur][wm16 + gid    ][kk + tg    ]);
            uint32_t a1 = __float_as_uint(As[cur][wm16 + gid + 8][kk + tg    ]);
            uint32_t a2 = __float_as_uint(As[cur][wm16 + gid    ][kk + tg + 4]);
            uint32_t a3 = __float_as_uint(As[cur][wm16 + gid + 8][kk + tg + 4]);
            #pragma unroll
            for (int t4i = 0; t4i < 4; t4i++) {
                const int col = wn32 + (t4i << 3) + gid;
                uint32_t b0 = __float_as_uint(Bs[cur][kk + tg    ][col]);
                uint32_t b1 = __float_as_uint(Bs[cur][kk + tg + 4][col]);
                asm volatile(
                    "mma.sync.aligned.m16n8k8.row.col.f32.tf32.tf32.f32 "
                    "{%0,%1,%2,%3}, {%4,%5,%6,%7}, {%8,%9}, {%0,%1,%2,%3};\n"
                    : "+f"(acc[t4i][0]), "+f"(acc[t4i][1]),
                      "+f"(acc[t4i][2]), "+f"(acc[t4i][3])
                    : "r"(a0), "r"(a1), "r"(a2), "r"(a3), "r"(b0), "r"(b1));
            }
        }
        if (more) sts(1 - cur);
        __syncthreads();
    }

    const int r0 = bm_ + wm16 + gid;
    const int r1 = r0 + 8;
    float cf0[E_], cf1[E_];
    #pragma unroll
    for (int e = 0; e < E_; e++) {
        cf0[e] = coeff[r0 * E_ + e];
        cf1[e] = coeff[r1 * E_ + e];
    }

    #pragma unroll
    for (int t = 0; t < 4; t++) {
        #pragma unroll
        for (int q = 0; q < 4; q++) {
            const int r  = (q < 2) ? r0 : r1;
            const int colL = wn32 + (t << 3) + (tg << 1) + (q & 1);
            const int cG = bn_ + colL;
            if ((N_ % 64) == 0 || cG < N_) {
                const float* cf = (q < 2) ? cf0 : cf1;
                float bb = 0.f;
                #pragma unroll
                for (int e = 0; e < E_; e++)
                    bb = fmaf(cf[e], __ldg(&bias[e * N_ + cG]), bb);
                float v = acc[t][q] + bb;
                if (ACT_ == 1) v = elu1(v);
                C[r * ldc + cG] = v;
            }
        }
    }
}

// ---------------- pack kernel: c -> q0 cols [32, 320) ----------------
__global__ void pack_c(const float* __restrict__ c, float* __restrict__ q0)
{
    int idx = blockIdx.x * blockDim.x + threadIdx.x;
    if (idx >= BATCH * 288) return;
    const int r = idx / 288;
    const int col = 32 + idx % 288;     // 32..319
    q0[r * 320 + col] = (col < IN0) ? c[r * FRAME + (col - 32)] : 0.f;
}

// ---------------- fused gate layer1 + layer2 + softmax (R2-proven) ---
__global__ __launch_bounds__(256) void gate12_softmax(
    const float* __restrict__ g1, const float* __restrict__ w1,
    const float* __restrict__ b1, const float* __restrict__ w2,
    const float* __restrict__ b2, float* __restrict__ coeff)
{
    __shared__ float w1s[64][65];
    __shared__ float w2s[64][8];
    __shared__ float b1s[64];
    __shared__ float g1s[32][64];
    __shared__ float g2s[32][65];

    const int tid = threadIdx.x;
    const int row0 = blockIdx.x * 32;

    for (int i = tid; i < 64 * 64; i += 256) w1s[i >> 6][i & 63] = w1[i];
    for (int i = tid; i < 64 * EXPERTS; i += 256) w2s[i / EXPERTS][i % EXPERTS] = w2[i];
    if (tid < 64) b1s[tid] = b1[tid];
    for (int i = tid; i < 32 * 64; i += 256)
        g1s[i >> 6][i & 63] = g1[(row0 + (i >> 6)) * GATE_H + (i & 63)];
    __syncthreads();

    const int ri = tid >> 3;
    const int c0 = (tid & 7) << 3;
    float acc[8];
    #pragma unroll
    for (int c = 0; c < 8; c++) acc[c] = b1s[c0 + c];
    #pragma unroll
    for (int k = 0; k < 64; k++) {
        const float gv = g1s[ri][k];
        #pragma unroll
        for (int c = 0; c < 8; c++) acc[c] = fmaf(gv, w1s[k][c0 + c], acc[c]);
    }
    #pragma unroll
    for (int c = 0; c < 8; c++) g2s[ri][c0 + c] = elu1(acc[c]);
    __syncthreads();

    if (tid < 32) {
        float lg[EXPERTS];
        #pragma unroll
        for (int e = 0; e < EXPERTS; e++) lg[e] = b2[e];
        #pragma unroll
        for (int k = 0; k < 64; k++) {
            const float gv = g2s[tid][k];
            #pragma unroll
            for (int e = 0; e < EXPERTS; e++) lg[e] = fmaf(gv, w2s[k][e], lg[e]);
        }
        float mx = lg[0];
        #pragma unroll
        for (int e = 1; e < EXPERTS; e++) mx = fmaxf(mx, lg[e]);
        float s = 0.f;
        #pragma unroll
        for (int e = 0; e < EXPERTS; e++) { lg[e] = expf(lg[e] - mx); s += lg[e]; }
        const float inv = 1.f / s;
        #pragma unroll
        for (int e = 0; e < EXPERTS; e++)
            coeff[(row0 + tid) * EXPERTS + e] = lg[e] * inv;
    }
}

// ---------------- launch ----------------
extern "C" void kernel_launch(void* const* d_in, const int* in_sizes, int n_in,
                              void* d_out, int out_size)
{
    const float* x       = (const float*)d_in[0];
    const float* c       = (const float*)d_in[1];
    const float* eps     = (const float*)d_in[2];
    const float* enc_w1  = (const float*)d_in[3];
    const float* enc_b1  = (const float*)d_in[4];
    const float* enc_w2  = (const float*)d_in[5];
    const float* enc_b2  = (const float*)d_in[6];
    const float* enc_wmu = (const float*)d_in[7];
    const float* enc_bmu = (const float*)d_in[8];
    const float* enc_wlv = (const float*)d_in[9];
    const float* enc_blv = (const float*)d_in[10];
    const float* gw0     = (const float*)d_in[11];
    const float* gb0     = (const float*)d_in[12];
    const float* gw1     = (const float*)d_in[13];
    const float* gb1     = (const float*)d_in[14];
    const float* gw2     = (const float*)d_in[15];
    const float* gb2     = (const float*)d_in[16];
    const float* w0      = (const float*)d_in[17];
    const float* b0      = (const float*)d_in[18];
    const float* w1      = (const float*)d_in[19];
    const float* b1      = (const float*)d_in[20];
    const float* w2      = (const float*)d_in[21];
    const float* b2      = (const float*)d_in[22];
    float* out = (float*)d_out;

    float *h1, *h2, *g1, *coef, *q0, *q1, *q2;
    cudaGetSymbolAddress((void**)&h1,   g_h1);
    cudaGetSymbolAddress((void**)&h2,   g_h2);
    cudaGetSymbolAddress((void**)&g1,   g_g1);
    cudaGetSymbolAddress((void**)&coef, g_coef);
    cudaGetSymbolAddress((void**)&q0,   g_q0);
    cudaGetSymbolAddress((void**)&q1,   g_q1);
    cudaGetSymbolAddress((void**)&q2,   g_q2);

    const dim3 blk(256);
    const dim3 gridH(HIDDEN / 64, BATCH / 64);              // (4, 64)
    const dim3 grid1(1, BATCH / 64);                        // (1, 64)
    const dim3 gridO((OUTD + 63) / 64, BATCH / 64);         // (5, 64)

    // pack c into q0 cols [32,320)
    pack_c<<<(BATCH * 288 + 255) / 256, 256>>>(c, q0);
    // encoder layer 1: h1 = elu([x, c] @ enc_w1 + b1)   K=534
    enc_gemm<HIDDEN, FRAME, 2*FRAME, 1><<<gridH, blk>>>(
        x, FRAME, c, FRAME, enc_w1, enc_b1, h1, HIDDEN);
    // encoder layer 2: h2 = elu([x, h1] @ enc_w2 + b2)  K=523
    enc_gemm<HIDDEN, FRAME, FRAME+HIDDEN, 1><<<gridH, blk>>>(
        x, FRAME, h1, HIDDEN, enc_w2, enc_b2, h2, HIDDEN);
    // mu|lv + fused z into q0/q1/q2
    dual_gemm<<<grid1, blk>>>(
        x, h2, enc_wmu, enc_bmu, enc_wlv, enc_blv, eps,
        out + OFF_MU, out + OFF_LV, q0, q1, q2);
    // gate0: g1 = elu(q0row @ gw0 + gb0), K=299 (q0 row is [z|c|pad])
    enc_gemm<GATE_H, 320, IN0, 1><<<grid1, blk>>>(
        q0, 320, q0, 320, gw0, gb0, g1, GATE_H);
    // gate1 + gate2 + softmax -> coeff
    gate12_softmax<<<BATCH / 32, blk>>>(g1, gw1, gb1, gw2, gb2, coef);
    // MoE decoder layer 0: DIN 299 (pad 320) -> d1 into q1 cols [32,288)
    dec_gemm<HIDDEN, IN0, 320, 320, 1><<<gridH, blk>>>(
        q0, coef, w0, b0, q1 + 32, IN1);
    // MoE decoder layer 1: DIN 288 exact -> d2 into q2 cols [32,288)
    dec_gemm<HIDDEN, IN1, 288, 288, 1><<<gridH, blk>>>(
        q1, coef, w1, b1, q2 + 32, IN1);
    // MoE decoder layer 2 (no act): N=267 -> output
    dec_gemm<OUTD, IN1, 288, 288, 0><<<gridO, blk>>>(
        q2, coef, w2, b2, out, OUTD);
}

// round 12
// speedup vs baseline: 2.8101x; 1.0143x over previous
#include <cuda_runtime.h>
#include <cstdint>

// ---------------- problem constants ----------------
#define BATCH   4096
#define FRAME   267
#define LATENT  32
#define HIDDEN  256
#define GATE_H  64
#define EXPERTS 6
#define IN0     (LATENT + FRAME)    // 299
#define IN1     (LATENT + HIDDEN)   // 288
#define OUTD    FRAME               // 267

#define OFF_MU  (BATCH * OUTD)
#define OFF_LV  (OFF_MU + BATCH * LATENT)

// ---------------- scratch (allocation-free) ----------------
__device__ float g_h1[BATCH * HIDDEN];
__device__ float g_h2[BATCH * HIDDEN];
__device__ float g_coef[BATCH * EXPERTS];
// packed decoder inputs (16B-aligned rows)
__device__ __align__(16) float g_q0[BATCH * 320];   // [z | c | 0pad]
__device__ __align__(16) float g_q1[BATCH * 288];   // [z | d1]
__device__ __align__(16) float g_q2[BATCH * 288];   // [z | d2]

__device__ __forceinline__ float elu1(float x) { return x > 0.f ? x : expm1f(x); }

__device__ __forceinline__ float tf32r(float x) {
    float y;
    asm("cvt.rna.tf32.f32 %0, %1;" : "=f"(y) : "f"(x));
    return y;
}

#define BK 32

// ============================================================
// Encoder GEMM — R10-proven (verbatim): double-buffered smem,
// single sync per k-tile. 64x64x32, 256 thr, warp tile m16n32.
// ============================================================
template<int N_, int K0_, int DIN_, int ACT_>
__global__ __launch_bounds__(256) void enc_gemm(
    const float* __restrict__ A0, int lda0,
    const float* __restrict__ A1, int lda1,
    const float* __restrict__ W, const float* __restrict__ bias,
    float* __restrict__ C, int ldc)
{
    constexpr int Ktot = DIN_;
    constexpr int NT   = (Ktot + BK - 1) / BK;
    __shared__ float As[2][64][36];
    __shared__ float Bs[2][32][72];

    const int tid  = threadIdx.x;
    const int lane = tid & 31;
    const int wid  = tid >> 5;
    const int wm16 = (wid >> 1) << 4;
    const int wn32 = (wid & 1) << 5;
    const int gid  = lane >> 2;
    const int tg   = lane & 3;

    const int bm_ = blockIdx.y * 64;
    const int bn_ = blockIdx.x * 64;

    const int amL = tid >> 3;
    const int akq = (tid & 7) << 2;
    const int bkL = tid >> 4;
    const int bnb = (tid & 15) << 2;

    float avv[2][4], bvv[2][4];

    auto ldgA = [&](int t) {
        const int kt = t * BK;
        #pragma unroll
        for (int half = 0; half < 2; half++) {
            const int m = bm_ + amL + half * 32;
            #pragma unroll
            for (int j = 0; j < 4; j++) {
                const int ig = kt + akq + j;
                float val = 0.f;
                if ((Ktot % BK == 0) || ig < Ktot)
                    val = (ig < K0_) ? __ldg(&A0[m * lda0 + ig])
                                     : __ldg(&A1[m * lda1 + (ig - K0_)]);
                avv[half][j] = val;
            }
        }
    };
    auto ldgB = [&](int t) {
        const int kt = t * BK;
        #pragma unroll
        for (int half = 0; half < 2; half++) {
            const int kg = kt + bkL + half * 16;
            const bool kok = (Ktot % BK == 0) || (kg < Ktot);
            #pragma unroll
            for (int j = 0; j < 4; j++) {
                const int n = bn_ + bnb + j;
                float val = 0.f;
                if (kok && ((N_ % 64) == 0 || n < N_))
                    val = __ldg(&W[(size_t)kg * N_ + n]);
                bvv[half][j] = val;
            }
        }
    };
    auto sts = [&](int buf) {
        #pragma unroll
        for (int half = 0; half < 2; half++) {
            const int mL = amL + half * 32;
            #pragma unroll
            for (int j = 0; j < 4; j++)
                As[buf][mL][akq + j] = tf32r(avv[half][j]);
        }
        #pragma unroll
        for (int half = 0; half < 2; half++) {
            const int kL = bkL + half * 16;
            #pragma unroll
            for (int j = 0; j < 4; j++)
                Bs[buf][kL][bnb + j] = tf32r(bvv[half][j]);
        }
    };

    float acc[4][4] = {};

    ldgA(0); ldgB(0);
    sts(0);
    __syncthreads();

    for (int t = 0; t < NT; t++) {
        const int cur = t & 1;
        const bool more = (t + 1 < NT);
        if (more) { ldgA(t + 1); ldgB(t + 1); }

        #pragma unroll
        for (int ks = 0; ks < 4; ks++) {
            const int kk = ks << 3;
            uint32_t a0 = __float_as_uint(As[cur][wm16 + gid    ][kk + tg    ]);
            uint32_t a1 = __float_as_uint(As[cur][wm16 + gid + 8][kk + tg    ]);
            uint32_t a2 = __float_as_uint(As[cur][wm16 + gid    ][kk + tg + 4]);
            uint32_t a3 = __float_as_uint(As[cur][wm16 + gid + 8][kk + tg + 4]);
            #pragma unroll
            for (int t4 = 0; t4 < 4; t4++) {
                const int col = wn32 + (t4 << 3) + gid;
                uint32_t b0 = __float_as_uint(Bs[cur][kk + tg    ][col]);
                uint32_t b1 = __float_as_uint(Bs[cur][kk + tg + 4][col]);
                asm volatile(
                    "mma.sync.aligned.m16n8k8.row.col.f32.tf32.tf32.f32 "
                    "{%0,%1,%2,%3}, {%4,%5,%6,%7}, {%8,%9}, {%0,%1,%2,%3};\n"
                    : "+f"(acc[t4][0]), "+f"(acc[t4][1]),
                      "+f"(acc[t4][2]), "+f"(acc[t4][3])
                    : "r"(a0), "r"(a1), "r"(a2), "r"(a3), "r"(b0), "r"(b1));
            }
        }
        if (more) sts(1 - cur);
        __syncthreads();
    }

    const int r0 = bm_ + wm16 + gid;
    const int r1 = r0 + 8;
    #pragma unroll
    for (int t = 0; t < 4; t++) {
        #pragma unroll
        for (int q = 0; q < 4; q++) {
            const int r  = (q < 2) ? r0 : r1;
            const int colL = wn32 + (t << 3) + (tg << 1) + (q & 1);
            const int cG = bn_ + colL;
            if ((N_ % 64) == 0 || cG < N_) {
                float v = acc[t][q] + __ldg(&bias[cG]);
                if (ACT_ == 1) v = elu1(v);
                C[r * ldc + cG] = v;
            }
        }
    }
}

// ============================================================
// mid2: dual GEMM (mu|lv, K=523) + z + gate0 GEMM (K=299) + gate1
// + gate2 + softmax — one launch, 64 rows/block, grid (1,64).
// FIX vs R11: gate0 reads z from smem (zsm) and c from the original
// read-only input — NEVER from q0 (which this kernel writes; reading
// it via the non-coherent __ldg path caused the R11 failure).
// ============================================================
__global__ __launch_bounds__(256) void mid2(
    const float* __restrict__ x,   const float* __restrict__ h2,
    const float* __restrict__ wmu, const float* __restrict__ bmu,
    const float* __restrict__ wlv, const float* __restrict__ blv,
    const float* __restrict__ epsv, const float* __restrict__ cc,
    const float* __restrict__ gw0, const float* __restrict__ gb0,
    const float* __restrict__ gw1, const float* __restrict__ gb1,
    const float* __restrict__ gw2, const float* __restrict__ gb2,
    float* __restrict__ mu_out, float* __restrict__ lv_out,
    float* __restrict__ q0, float* __restrict__ q1, float* __restrict__ q2,
    float* __restrict__ coeff)
{
    __shared__ float As[2][64][36];     // GEMM A tiles; overlays: muS, g2s
    __shared__ float Bs[2][32][72];     // GEMM B tiles; overlays: lvS, w1s
    __shared__ float g1s[64][65];
    __shared__ float zsm[64][33];       // block-local z (phase A -> phase B)

    const int tid  = threadIdx.x;
    const int lane = tid & 31;
    const int wid  = tid >> 5;
    const int wm16 = (wid >> 1) << 4;
    const int wn32 = (wid & 1) << 5;
    const int gid  = lane >> 2;
    const int tg   = lane & 3;

    const int bm_ = blockIdx.y * 64;

    const int amL = tid >> 3;
    const int akq = (tid & 7) << 2;
    const int bkL = tid >> 4;
    const int bnb = (tid & 15) << 2;

    const int r0 = bm_ + wm16 + gid;
    const int r1 = r0 + 8;

    float avv[2][4], bvv[2][4];

    auto sts = [&](int buf) {
        #pragma unroll
        for (int half = 0; half < 2; half++) {
            const int mL = amL + half * 32;
            #pragma unroll
            for (int j = 0; j < 4; j++)
                As[buf][mL][akq + j] = tf32r(avv[half][j]);
        }
        #pragma unroll
        for (int half = 0; half < 2; half++) {
            const int kL = bkL + half * 16;
            #pragma unroll
            for (int j = 0; j < 4; j++)
                Bs[buf][kL][bnb + j] = tf32r(bvv[half][j]);
        }
    };

    // =============== Phase A: dual GEMM mu|lv, K=523 ===============
    {
        constexpr int Ktot = FRAME + HIDDEN;            // 523
        constexpr int NT   = (Ktot + BK - 1) / BK;      // 17

        auto ldgA = [&](int t) {
            const int kt = t * BK;
            #pragma unroll
            for (int half = 0; half < 2; half++) {
                const int m = bm_ + amL + half * 32;
                #pragma unroll
                for (int j = 0; j < 4; j++) {
                    const int ig = kt + akq + j;
                    float val = 0.f;
                    if (ig < Ktot)
                        val = (ig < FRAME) ? __ldg(&x[m * FRAME + ig])
                                           : __ldg(&h2[m * HIDDEN + (ig - FRAME)]);
                    avv[half][j] = val;
                }
            }
        };
        auto ldgB = [&](int t) {
            const int kt = t * BK;
            #pragma unroll
            for (int half = 0; half < 2; half++) {
                const int kg = kt + bkL + half * 16;
                const bool kok = kg < Ktot;
                #pragma unroll
                for (int j = 0; j < 4; j++) {
                    const int nl = bnb + j;
                    float val = 0.f;
                    if (kok)
                        val = (nl < 32) ? __ldg(&wmu[kg * 32 + nl])
                                        : __ldg(&wlv[kg * 32 + (nl - 32)]);
                    bvv[half][j] = val;
                }
            }
        };

        float acc[4][4] = {};
        ldgA(0); ldgB(0);
        sts(0);
        __syncthreads();

        for (int t = 0; t < NT; t++) {
            const int cur = t & 1;
            const bool more = (t + 1 < NT);
            if (more) { ldgA(t + 1); ldgB(t + 1); }

            #pragma unroll
            for (int ks = 0; ks < 4; ks++) {
                const int kk = ks << 3;
                uint32_t a0 = __float_as_uint(As[cur][wm16 + gid    ][kk + tg    ]);
                uint32_t a1 = __float_as_uint(As[cur][wm16 + gid + 8][kk + tg    ]);
                uint32_t a2 = __float_as_uint(As[cur][wm16 + gid    ][kk + tg + 4]);
                uint32_t a3 = __float_as_uint(As[cur][wm16 + gid + 8][kk + tg + 4]);
                #pragma unroll
                for (int t4 = 0; t4 < 4; t4++) {
                    const int col = wn32 + (t4 << 3) + gid;
                    uint32_t b0 = __float_as_uint(Bs[cur][kk + tg    ][col]);
                    uint32_t b1 = __float_as_uint(Bs[cur][kk + tg + 4][col]);
                    asm volatile(
                        "mma.sync.aligned.m16n8k8.row.col.f32.tf32.tf32.f32 "
                        "{%0,%1,%2,%3}, {%4,%5,%6,%7}, {%8,%9}, {%0,%1,%2,%3};\n"
                        : "+f"(acc[t4][0]), "+f"(acc[t4][1]),
                          "+f"(acc[t4][2]), "+f"(acc[t4][3])
                        : "r"(a0), "r"(a1), "r"(a2), "r"(a3), "r"(b0), "r"(b1));
                }
            }
            if (more) sts(1 - cur);
            __syncthreads();
        }

        // epilogue: mu/lv out + smem (overlays on As[0]/Bs[0])
        float* muS = &As[0][0][0];
        float* lvS = &Bs[0][0][0];

        #pragma unroll
        for (int t = 0; t < 4; t++) {
            #pragma unroll
            for (int q = 0; q < 4; q++) {
                const int r  = (q < 2) ? r0 : r1;
                const int rL = r - bm_;
                const int colL = wn32 + (t << 3) + (tg << 1) + (q & 1);
                if (colL < 32) {
                    const float m_ = acc[t][q] + __ldg(&bmu[colL]);
                    mu_out[r * 32 + colL] = m_;
                    muS[rL * 33 + colL] = m_;
                } else {
                    const int cl = colL - 32;
                    const float l_ = acc[t][q] + __ldg(&blv[cl]);
                    lv_out[r * 32 + cl] = l_;
                    lvS[rL * 33 + cl] = l_;
                }
            }
        }
        __syncthreads();

        // z = mu + eps*exp(0.5*lv) -> zsm (for phase B) + q0/q1/q2 (global)
        for (int e = tid; e < 64 * 32; e += 256) {
            const int rL = e >> 5, cl = e & 31;
            const int r = bm_ + rL;
            const float zv = fmaf(__ldg(&epsv[r * 32 + cl]),
                                  expf(0.5f * lvS[rL * 33 + cl]), muS[rL * 33 + cl]);
            zsm[rL][cl] = zv;
            q0[r * 320 + cl] = zv;
            q1[r * 288 + cl] = zv;
            q2[r * 288 + cl] = zv;
        }
        __syncthreads();   // fence before As/Bs reuse; zsm visible to all
    }

    // =============== Phase B: gate0 GEMM, K=299, N=64 ===============
    {
        constexpr int Ktot = IN0;                        // 299
        constexpr int NT   = (Ktot + BK - 1) / BK;       // 10

        auto ldgA = [&](int t) {
            const int kt = t * BK;
            #pragma unroll
            for (int half = 0; half < 2; half++) {
                const int mL = amL + half * 32;
                const int m  = bm_ + mL;
                #pragma unroll
                for (int j = 0; j < 4; j++) {
                    const int ig = kt + akq + j;
                    float val = 0.f;
                    if (ig < 32)            val = zsm[mL][ig];
                    else if (ig < Ktot)     val = __ldg(&cc[m * FRAME + (ig - 32)]);
                    avv[half][j] = val;
                }
            }
        };
        auto ldgB = [&](int t) {
            const int kt = t * BK;
            #pragma unroll
            for (int half = 0; half < 2; half++) {
                const int kg = kt + bkL + half * 16;
                const bool kok = kg < Ktot;
                #pragma unroll
                for (int j = 0; j < 4; j++) {
                    const int nl = bnb + j;
                    bvv[half][j] = kok ? __ldg(&gw0[kg * 64 + nl]) : 0.f;
                }
            }
        };

        float acc[4][4] = {};
        ldgA(0); ldgB(0);
        sts(0);
        __syncthreads();

        for (int t = 0; t < NT; t++) {
            const int cur = t & 1;
            const bool more = (t + 1 < NT);
            if (more) { ldgA(t + 1); ldgB(t + 1); }

            #pragma unroll
            for (int ks = 0; ks < 4; ks++) {
                const int kk = ks << 3;
                uint32_t a0 = __float_as_uint(As[cur][wm16 + gid    ][kk + tg    ]);
                uint32_t a1 = __float_as_uint(As[cur][wm16 + gid + 8][kk + tg    ]);
                uint32_t a2 = __float_as_uint(As[cur][wm16 + gid    ][kk + tg + 4]);
                uint32_t a3 = __float_as_uint(As[cur][wm16 + gid + 8][kk + tg + 4]);
                #pragma unroll
                for (int t4 = 0; t4 < 4; t4++) {
                    const int col = wn32 + (t4 << 3) + gid;
                    uint32_t b0 = __float_as_uint(Bs[cur][kk + tg    ][col]);
                    uint32_t b1 = __float_as_uint(Bs[cur][kk + tg + 4][col]);
                    asm volatile(
                        "mma.sync.aligned.m16n8k8.row.col.f32.tf32.tf32.f32 "
                        "{%0,%1,%2,%3}, {%4,%5,%6,%7}, {%8,%9}, {%0,%1,%2,%3};\n"
                        : "+f"(acc[t4][0]), "+f"(acc[t4][1]),
                          "+f"(acc[t4][2]), "+f"(acc[t4][3])
                        : "r"(a0), "r"(a1), "r"(a2), "r"(a3), "r"(b0), "r"(b1));
                }
            }
            if (more) sts(1 - cur);
            __syncthreads();
        }

        // epilogue -> g1s (smem)
        #pragma unroll
        for (int t = 0; t < 4; t++) {
            #pragma unroll
            for (int q = 0; q < 4; q++) {
                const int rL = ((q < 2) ? r0 : r1) - bm_;
                const int colL = wn32 + (t << 3) + (tg << 1) + (q & 1);
                g1s[rL][colL] = elu1(acc[t][q] + __ldg(&gb0[colL]));
            }
        }
        __syncthreads();
    }

    // =============== Phase C: gate1 (64x64), w1 overlay on Bs ========
    {
        float* w1f = &Bs[0][0][0];            // [64][72] = 4608 floats exactly
        for (int i = tid; i < 64 * 64; i += 256)
            w1f[(i >> 6) * 72 + (i & 63)] = __ldg(&gw1[i]);
        __syncthreads();

        float* g2f = &As[0][0][0];            // [64][65] = 4160 <= 4608
        const int row = tid >> 2;             // 0..63
        const int cs  = tid & 3;
        float a16[16];
        #pragma unroll
        for (int j = 0; j < 16; j++) a16[j] = __ldg(&gb1[cs + (j << 2)]);
        #pragma unroll
        for (int k = 0; k < 64; k++) {
            const float gv = g1s[row][k];
            #pragma unroll
            for (int j = 0; j < 16; j++)
                a16[j] = fmaf(gv, w1f[k * 72 + cs + (j << 2)], a16[j]);
        }
        #pragma unroll
        for (int j = 0; j < 16; j++)
            g2f[row * 65 + cs + (j << 2)] = elu1(a16[j]);
        __syncthreads();
    }

    // =============== Phase D: gate2 + softmax -> coeff ===============
    if (tid < 64) {
        const float* g2f = &As[0][0][0];
        float lg[EXPERTS];
        #pragma unroll
        for (int e = 0; e < EXPERTS; e++) lg[e] = __ldg(&gb2[e]);
        #pragma unroll
        for (int k = 0; k < 64; k++) {
            const float gv = g2f[tid * 65 + k];
            #pragma unroll
            for (int e = 0; e < EXPERTS; e++)
                lg[e] = fmaf(gv, __ldg(&gw2[k * EXPERTS + e]), lg[e]);
        }
        float mx = lg[0];
        #pragma unroll
        for (int e = 1; e < EXPERTS; e++) mx = fmaxf(mx, lg[e]);
        float s = 0.f;
        #pragma unroll
        for (int e = 0; e < EXPERTS; e++) { lg[e] = expf(lg[e] - mx); s += lg[e]; }
        const float inv = 1.f / s;
        #pragma unroll
        for (int e = 0; e < EXPERTS; e++)
            coeff[(bm_ + tid) * EXPERTS + e] = lg[e] * inv;
    }
}

// ============================================================
// Decoder GEMM — R10-proven (verbatim): packed A, double-buffered.
// ============================================================
template<int N_, int DINR_, int DINP_, int LDA_, int ACT_>
__global__ __launch_bounds__(256) void dec_gemm(
    const float* __restrict__ A,
    const float* __restrict__ coeff,
    const float* __restrict__ W, const float* __restrict__ bias,
    float* __restrict__ C, int ldc)
{
    constexpr int E_  = EXPERTS;
    constexpr int TPE = DINP_ / 32;
    constexpr int NT  = E_ * TPE;
    __shared__ __align__(16) float As[2][64][36];
    __shared__ __align__(16) float Bs[2][32][72];

    const int tid  = threadIdx.x;
    const int lane = tid & 31;
    const int wid  = tid >> 5;
    const int wm16 = (wid >> 1) << 4;
    const int wn32 = (wid & 1) << 5;
    const int gid  = lane >> 2;
    const int tg   = lane & 3;

    const int bm_ = blockIdx.y * 64;
    const int bn_ = blockIdx.x * 64;

    const int amL = tid >> 3;
    const int akq = (tid & 7) << 2;
    const int bkL = tid >> 4;
    const int bnb = (tid & 15) << 2;

    const float* Ar0  = A + (bm_ + amL) * LDA_;
    const float* Ar1  = Ar0 + 32 * LDA_;
    const float* cf0p = coeff + (bm_ + amL) * E_;
    const float* cf1p = cf0p + 32 * E_;

    float avv[2][4], bvv[2][4];

    auto ldgA = [&](int t) {
        const int e  = t / TPE;
        const int i0 = (t - e * TPE) * 32 + akq;
        const float c0 = __ldg(&cf0p[e]);
        const float c1 = __ldg(&cf1p[e]);
        const float4 v0 = __ldg(reinterpret_cast<const float4*>(Ar0 + i0));
        const float4 v1 = __ldg(reinterpret_cast<const float4*>(Ar1 + i0));
        avv[0][0] = v0.x * c0; avv[0][1] = v0.y * c0; avv[0][2] = v0.z * c0; avv[0][3] = v0.w * c0;
        avv[1][0] = v1.x * c1; avv[1][1] = v1.y * c1; avv[1][2] = v1.z * c1; avv[1][3] = v1.w * c1;
    };
    auto ldgB = [&](int t) {
        const int e  = t / TPE;
        const int k0 = (t - e * TPE) * 32;
        const float* We = W + (size_t)e * DINR_ * N_;
        #pragma unroll
        for (int half = 0; half < 2; half++) {
            const int kl = k0 + bkL + half * 16;
            const bool kok = (DINR_ == DINP_) || (kl < DINR_);
            if ((N_ % 64) == 0) {
                float4 v = make_float4(0.f, 0.f, 0.f, 0.f);
                if (kok)
                    v = __ldg(reinterpret_cast<const float4*>(We + (size_t)kl * N_ + bn_ + bnb));
                bvv[half][0] = v.x; bvv[half][1] = v.y; bvv[half][2] = v.z; bvv[half][3] = v.w;
            } else {
                #pragma unroll
                for (int j = 0; j < 4; j++) {
                    const int n = bn_ + bnb + j;
                    float v = 0.f;
                    if (kok && n < N_) v = __ldg(&We[(size_t)kl * N_ + n]);
                    bvv[half][j] = v;
                }
            }
        }
    };
    auto sts = [&](int buf) {
        #pragma unroll
        for (int half = 0; half < 2; half++) {
            const float4 t4 = make_float4(tf32r(avv[half][0]), tf32r(avv[half][1]),
                                          tf32r(avv[half][2]), tf32r(avv[half][3]));
            *reinterpret_cast<float4*>(&As[buf][amL + half * 32][akq]) = t4;
        }
        #pragma unroll
        for (int half = 0; half < 2; half++) {
            const float4 t4 = make_float4(tf32r(bvv[half][0]), tf32r(bvv[half][1]),
                                          tf32r(bvv[half][2]), tf32r(bvv[half][3]));
            *reinterpret_cast<float4*>(&Bs[buf][bkL + half * 16][bnb]) = t4;
        }
    };

    float acc[4][4] = {};

    ldgA(0); ldgB(0);
    sts(0);
    __syncthreads();

    for (int t = 0; t < NT; t++) {
        const int cur = t & 1;
        const bool more = (t + 1 < NT);
        if (more) { ldgA(t + 1); ldgB(t + 1); }

        #pragma unroll
        for (int ks = 0; ks < 4; ks++) {
            const int kk = ks << 3;
            uint32_t a0 = __float_as_uint(As[cur][wm16 + gid    ][kk + tg    ]);
            uint32_t a1 = __float_as_uint(As[cur][wm16 + gid + 8][kk + tg    ]);
            uint32_t a2 = __float_as_uint(As[cur][wm16 + gid    ][kk + tg + 4]);
            uint32_t a3 = __float_as_uint(As[cur][wm16 + gid + 8][kk + tg + 4]);
            #pragma unroll
            for (int t4i = 0; t4i < 4; t4i++) {
                const int col = wn32 + (t4i << 3) + gid;
                uint32_t b0 = __float_as_uint(Bs[cur][kk + tg    ][col]);
                uint32_t b1 = __float_as_uint(Bs[cur][kk + tg + 4][col]);
                asm volatile(
                    "mma.sync.aligned.m16n8k8.row.col.f32.tf32.tf32.f32 "
                    "{%0,%1,%2,%3}, {%4,%5,%6,%7}, {%8,%9}, {%0,%1,%2,%3};\n"
                    : "+f"(acc[t4i][0]), "+f"(acc[t4i][1]),
                      "+f"(acc[t4i][2]), "+f"(acc[t4i][3])
                    : "r"(a0), "r"(a1), "r"(a2), "r"(a3), "r"(b0), "r"(b1));
            }
        }
        if (more) sts(1 - cur);
        __syncthreads();
    }

    const int r0 = bm_ + wm16 + gid;
    const int r1 = r0 + 8;
    float cf0[E_], cf1[E_];
    #pragma unroll
    for (int e = 0; e < E_; e++) {
        cf0[e] = coeff[r0 * E_ + e];
        cf1[e] = coeff[r1 * E_ + e];
    }

    #pragma unroll
    for (int t = 0; t < 4; t++) {
        #pragma unroll
        for (int q = 0; q < 4; q++) {
            const int r  = (q < 2) ? r0 : r1;
            const int colL = wn32 + (t << 3) + (tg << 1) + (q & 1);
            const int cG = bn_ + colL;
            if ((N_ % 64) == 0 || cG < N_) {
                const float* cf = (q < 2) ? cf0 : cf1;
                float bb = 0.f;
                #pragma unroll
                for (int e = 0; e < E_; e++)
                    bb = fmaf(cf[e], __ldg(&bias[e * N_ + cG]), bb);
                float v = acc[t][q] + bb;
                if (ACT_ == 1) v = elu1(v);
                C[r * ldc + cG] = v;
            }
        }
    }
}

// ---------------- pack kernel: c -> q0 cols [32, 320) ----------------
__global__ void pack_c(const float* __restrict__ c, float* __restrict__ q0)
{
    int idx = blockIdx.x * blockDim.x + threadIdx.x;
    if (idx >= BATCH * 288) return;
    const int r = idx / 288;
    const int col = 32 + idx % 288;     // 32..319
    q0[r * 320 + col] = (col < IN0) ? c[r * FRAME + (col - 32)] : 0.f;
}

// ---------------- launch ----------------
extern "C" void kernel_launch(void* const* d_in, const int* in_sizes, int n_in,
                              void* d_out, int out_size)
{
    const float* x       = (const float*)d_in[0];
    const float* c       = (const float*)d_in[1];
    const float* eps     = (const float*)d_in[2];
    const float* enc_w1  = (const float*)d_in[3];
    const float* enc_b1  = (const float*)d_in[4];
    const float* enc_w2  = (const float*)d_in[5];
    const float* enc_b2  = (const float*)d_in[6];
    const float* enc_wmu = (const float*)d_in[7];
    const float* enc_bmu = (const float*)d_in[8];
    const float* enc_wlv = (const float*)d_in[9];
    const float* enc_blv = (const float*)d_in[10];
    const float* gw0     = (const float*)d_in[11];
    const float* gb0     = (const float*)d_in[12];
    const float* gw1     = (const float*)d_in[13];
    const float* gb1     = (const float*)d_in[14];
    const float* gw2     = (const float*)d_in[15];
    const float* gb2     = (const float*)d_in[16];
    const float* w0      = (const float*)d_in[17];
    const float* b0      = (const float*)d_in[18];
    const float* w1      = (const float*)d_in[19];
    const float* b1      = (const float*)d_in[20];
    const float* w2      = (const float*)d_in[21];
    const float* b2      = (const float*)d_in[22];
    float* out = (float*)d_out;

    float *h1, *h2, *coef, *q0, *q1, *q2;
    cudaGetSymbolAddress((void**)&h1,   g_h1);
    cudaGetSymbolAddress((void**)&h2,   g_h2);
    cudaGetSymbolAddress((void**)&coef, g_coef);
    cudaGetSymbolAddress((void**)&q0,   g_q0);
    cudaGetSymbolAddress((void**)&q1,   g_q1);
    cudaGetSymbolAddress((void**)&q2,   g_q2);

    const dim3 blk(256);
    const dim3 gridH(HIDDEN / 64, BATCH / 64);              // (4, 64)
    const dim3 grid1(1, BATCH / 64);                        // (1, 64)
    const dim3 gridO((OUTD + 63) / 64, BATCH / 64);         // (5, 64)

    // pack c into q0 cols [32,320)
    pack_c<<<(BATCH * 288 + 255) / 256, 256>>>(c, q0);
    // encoder layer 1: h1 = elu([x, c] @ enc_w1 + b1)   K=534
    enc_gemm<HIDDEN, FRAME, 2*FRAME, 1><<<gridH, blk>>>(
        x, FRAME, c, FRAME, enc_w1, enc_b1, h1, HIDDEN);
    // encoder layer 2: h2 = elu([x, h1] @ enc_w2 + b2)  K=523
    enc_gemm<HIDDEN, FRAME, FRAME+HIDDEN, 1><<<gridH, blk>>>(
        x, FRAME, h1, HIDDEN, enc_w2, enc_b2, h2, HIDDEN);
    // mid2: mu/lv + z + gate0 + gate1 + gate2 + softmax (one launch)
    mid2<<<grid1, blk>>>(
        x, h2, enc_wmu, enc_bmu, enc_wlv, enc_blv, eps, c,
        gw0, gb0, gw1, gb1, gw2, gb2,
        out + OFF_MU, out + OFF_LV, q0, q1, q2, coef);
    // MoE decoder layer 0: DIN 299 (pad 320) -> d1 into q1 cols [32,288)
    dec_gemm<HIDDEN, IN0, 320, 320, 1><<<gridH, blk>>>(
        q0, coef, w0, b0, q1 + 32, IN1);
    // MoE decoder layer 1: DIN 288 exact -> d2 into q2 cols [32,288)
    dec_gemm<HIDDEN, IN1, 288, 288, 1><<<gridH, blk>>>(
        q1, coef, w1, b1, q2 + 32, IN1);
    // MoE decoder layer 2 (no act): N=267 -> output
    dec_gemm<OUTD, IN1, 288, 288, 0><<<gridO, blk>>>(
        q2, coef, w2, b2, out, OUTD);
}